// round 1
// baseline (speedup 1.0000x reference)
#include <cuda_runtime.h>
#include <math.h>

// Problem constants
#define T_TOK 16384          // B*N tokens
#define TK    32768          // T*K slots
#define NE    8              // experts
#define KSEL  2
#define CDIM  1024
#define INTER 2730
#define N2    5460           // 2*INTER
#define CAP   2560           // int(1.25*T/E)

// GEMM tiling
#define BM 128
#define BN 64
#define BK 16
#define PAD 4

// ---------------- scratch (device globals; no allocations) ----------------
__device__ unsigned long long g_key[TK];
__device__ int   g_eid[TK];
__device__ float g_val[TK];
__device__ unsigned long long g_thresh[NE];
__device__ int   g_cnt[NE];
__device__ int   g_tok[NE][CAP];
__device__ float g_w[NE][CAP];
__device__ float g_act[(size_t)NE * CAP * INTER];   // ~224 MB

// ---------------- kernel 0: init ----------------
__global__ void k0_init(float* out, int out_size) {
    int i = blockIdx.x * blockDim.x + threadIdx.x;
    int stride = gridDim.x * blockDim.x;
    for (int j = i; j < out_size; j += stride) out[j] = 0.0f;
    if (i < NE) g_cnt[i] = 0;
    for (int j = i; j < NE * CAP; j += stride) {
        ((int*)g_tok)[j] = 0;
        ((float*)g_w)[j] = 0.0f;
    }
}

// ---------------- kernel 1: gating (one warp per token) ----------------
__global__ void k1_gate(const float* __restrict__ x, const float* __restrict__ cond,
                        const float* __restrict__ snr, const float* __restrict__ gw) {
    int warp = (blockIdx.x * blockDim.x + threadIdx.x) >> 5;
    int lane = threadIdx.x & 31;
    if (warp >= T_TOK) return;
    int t = warp;
    int b = t >> 12;   // / 4096

    float acc[NE];
#pragma unroll
    for (int e = 0; e < NE; ++e) acc[e] = 0.0f;

    const float* xr = x + (size_t)t * CDIM;
    const float* cr = cond + (size_t)b * CDIM;
    for (int d = lane; d < 2 * CDIM; d += 32) {
        float v = (d < CDIM) ? xr[d] : cr[d - CDIM];
        const float* wrow = gw + (size_t)d * NE;
#pragma unroll
        for (int e = 0; e < NE; ++e) acc[e] += v * wrow[e];
    }
#pragma unroll
    for (int e = 0; e < NE; ++e) {
#pragma unroll
        for (int o = 16; o > 0; o >>= 1)
            acc[e] += __shfl_xor_sync(0xFFFFFFFFu, acc[e], o);
    }

    if (lane == 0) {
        bool hn = snr[b] < 0.5f;
        float lg[NE];
#pragma unroll
        for (int e = 0; e < NE; ++e)
            lg[e] = (hn && e >= 2) ? -INFINITY : acc[e];

        float mx = lg[0];
#pragma unroll
        for (int e = 1; e < NE; ++e) mx = fmaxf(mx, lg[e]);
        float p[NE], s = 0.0f;
#pragma unroll
        for (int e = 0; e < NE; ++e) { p[e] = expf(lg[e] - mx); s += p[e]; }
        float inv = 1.0f / s;
#pragma unroll
        for (int e = 0; e < NE; ++e) p[e] *= inv;

        // top-2, ties -> lower index (matches lax.top_k)
        int i0 = 0; float p0 = p[0];
#pragma unroll
        for (int e = 1; e < NE; ++e) if (p[e] > p0) { p0 = p[e]; i0 = e; }
        int i1 = -1; float p1 = -1.0f;
#pragma unroll
        for (int e = 0; e < NE; ++e) if (e != i0 && p[e] > p1) { p1 = p[e]; i1 = e; }

        float denom = fmaxf(p0 + p1, 1e-12f);
        float w0 = p0 / denom, w1 = p1 / denom;

        int s0 = t * 2, s1 = t * 2 + 1;
        g_eid[s0] = i0; g_val[s0] = w0;
        g_key[s0] = ((unsigned long long)__float_as_uint(w0) << 32) |
                    (unsigned long long)(0xFFFFFFFFu - (unsigned)s0);
        g_eid[s1] = i1; g_val[s1] = w1;
        g_key[s1] = ((unsigned long long)__float_as_uint(w1) << 32) |
                    (unsigned long long)(0xFFFFFFFFu - (unsigned)s1);
    }
}

// ---------------- kernel 2: per-expert exact radix select ----------------
__global__ void k2_select() {
    int e = blockIdx.x;
    int tid = threadIdx.x;
    __shared__ int hist[256];
    __shared__ unsigned long long sh_prefix;
    __shared__ int sh_rem;
    __shared__ int sh_n;

    int cnt = 0;
    for (int s = tid; s < TK; s += 256) if (g_eid[s] == e) cnt++;
    if (tid == 0) sh_n = 0;
    __syncthreads();
    atomicAdd(&sh_n, cnt);
    __syncthreads();
    int n = sh_n;

    if (n <= CAP) {
        if (tid == 0) g_thresh[e] = 0ULL;   // select everything assigned to e
        return;
    }

    if (tid == 0) { sh_prefix = 0ULL; sh_rem = CAP; }
    __syncthreads();

    for (int p = 7; p >= 0; --p) {
        if (tid < 256) hist[tid] = 0;
        __syncthreads();
        unsigned long long prefix = sh_prefix;
        int shift_lo = p * 8;
        for (int s = tid; s < TK; s += 256) {
            if (g_eid[s] != e) continue;
            unsigned long long key = g_key[s];
            bool match = (p == 7) || (((key ^ prefix) >> ((p + 1) * 8)) == 0ULL);
            if (match)
                atomicAdd(&hist[(int)((key >> shift_lo) & 255ULL)], 1);
        }
        __syncthreads();
        if (tid == 0) {
            int rem = sh_rem;
            int cum = 0, d = 255;
            for (; d > 0; --d) { cum += hist[d]; if (cum >= rem) break; }
            if (cum < rem) cum += hist[0];   // d == 0 fall-through
            sh_prefix |= ((unsigned long long)d) << shift_lo;
            sh_rem = rem - (cum - hist[d]);
        }
        __syncthreads();
    }
    if (tid == 0) g_thresh[e] = sh_prefix;
}

// ---------------- kernel 3: compaction into per-expert lists ----------------
__global__ void k3_compact() {
    int s = blockIdx.x * blockDim.x + threadIdx.x;
    if (s >= TK) return;
    int e = g_eid[s];
    if (g_key[s] >= g_thresh[e]) {
        int pos = atomicAdd(&g_cnt[e], 1);
        if (pos < CAP) {   // exact by construction; guard for safety
            g_tok[e][pos] = s >> 1;
            g_w[e][pos] = g_val[s];
        }
    }
}

// ---------------- kernel 4: gather + gate_up GEMM + SiLU*up ----------------
__global__ __launch_bounds__(256)
void k4_gemm1(const float* __restrict__ x, const float* __restrict__ wgu) {
    int e  = blockIdx.z;
    int m0 = blockIdx.x * BM;
    int n0 = blockIdx.y * BN;

    __shared__ float As[BK][BM + PAD];
    __shared__ float Bg[BK][BN];
    __shared__ float Bu[BK][BN];

    int tid = threadIdx.x;
    int trow = tid >> 4;        // 0..15 -> M
    int tcol = tid & 15;        // 0..15 -> N

    float accG[8][4] = {{0}}, accU[8][4] = {{0}};

    const int* toks = g_tok[e];
    const float* wg = wgu + (size_t)e * CDIM * N2;

    for (int k0 = 0; k0 < CDIM; k0 += BK) {
#pragma unroll
        for (int i = 0; i < 8; ++i) {
            int idx = i * 256 + tid;
            int mm = idx >> 4;
            int kk = idx & 15;
            int tok = toks[m0 + mm];
            As[kk][mm] = x[(size_t)tok * CDIM + k0 + kk];
        }
#pragma unroll
        for (int i = 0; i < 4; ++i) {
            int idx = i * 256 + tid;
            int nn = idx & 63;
            int kk = idx >> 6;
            int n = n0 + nn;
            float vg = 0.0f, vu = 0.0f;
            if (n < INTER) {
                size_t base = (size_t)(k0 + kk) * N2 + n;
                vg = wg[base];
                vu = wg[base + INTER];
            }
            Bg[kk][nn] = vg;
            Bu[kk][nn] = vu;
        }
        __syncthreads();
#pragma unroll
        for (int kk = 0; kk < BK; ++kk) {
            float ra[8], rg[4], ru[4];
#pragma unroll
            for (int i = 0; i < 8; ++i) ra[i] = As[kk][trow * 8 + i];
#pragma unroll
            for (int j = 0; j < 4; ++j) { rg[j] = Bg[kk][tcol * 4 + j]; ru[j] = Bu[kk][tcol * 4 + j]; }
#pragma unroll
            for (int i = 0; i < 8; ++i)
#pragma unroll
                for (int j = 0; j < 4; ++j) {
                    accG[i][j] += ra[i] * rg[j];
                    accU[i][j] += ra[i] * ru[j];
                }
        }
        __syncthreads();
    }

    float* outA = g_act + (size_t)e * CAP * INTER;
#pragma unroll
    for (int i = 0; i < 8; ++i) {
        int m = m0 + trow * 8 + i;
#pragma unroll
        for (int j = 0; j < 4; ++j) {
            int n = n0 + tcol * 4 + j;
            if (n < INTER) {
                float gg = accG[i][j];
                float a = gg / (1.0f + expf(-gg)) * accU[i][j];
                outA[(size_t)m * INTER + n] = a;
            }
        }
    }
}

// ---------------- kernel 5: down GEMM + weight scale + scatter ----------------
__global__ __launch_bounds__(256)
void k5_gemm2(const float* __restrict__ wd, float* __restrict__ out) {
    int e  = blockIdx.z;
    int m0 = blockIdx.x * BM;
    int n0 = blockIdx.y * BN;

    __shared__ float As[BK][BM + PAD];
    __shared__ float Bs[BK][BN];

    int tid = threadIdx.x;
    int trow = tid >> 4;
    int tcol = tid & 15;

    float acc[8][4] = {{0}};

    const float* A = g_act + (size_t)e * CAP * INTER;
    const float* B = wd + (size_t)e * INTER * CDIM;

    for (int k0 = 0; k0 < INTER; k0 += BK) {
#pragma unroll
        for (int i = 0; i < 8; ++i) {
            int idx = i * 256 + tid;
            int mm = idx >> 4;
            int kk = idx & 15;
            int k = k0 + kk;
            As[kk][mm] = (k < INTER) ? A[(size_t)(m0 + mm) * INTER + k] : 0.0f;
        }
#pragma unroll
        for (int i = 0; i < 4; ++i) {
            int idx = i * 256 + tid;
            int nn = idx & 63;
            int kk = idx >> 6;
            int k = k0 + kk;
            Bs[kk][nn] = (k < INTER) ? B[(size_t)k * CDIM + n0 + nn] : 0.0f;
        }
        __syncthreads();
#pragma unroll
        for (int kk = 0; kk < BK; ++kk) {
            float ra[8], rb[4];
#pragma unroll
            for (int i = 0; i < 8; ++i) ra[i] = As[kk][trow * 8 + i];
#pragma unroll
            for (int j = 0; j < 4; ++j) rb[j] = Bs[kk][tcol * 4 + j];
#pragma unroll
            for (int i = 0; i < 8; ++i)
#pragma unroll
                for (int j = 0; j < 4; ++j) acc[i][j] += ra[i] * rb[j];
        }
        __syncthreads();
    }

#pragma unroll
    for (int i = 0; i < 8; ++i) {
        int m = m0 + trow * 8 + i;
        float w = g_w[e][m];
        if (w == 0.0f) continue;   // padding rows contribute nothing
        int tok = g_tok[e][m];
        float* orow = out + (size_t)tok * CDIM;
#pragma unroll
        for (int j = 0; j < 4; ++j) {
            int n = n0 + tcol * 4 + j;
            atomicAdd(&orow[n], acc[i][j] * w);
        }
    }
}

// ---------------- launch ----------------
extern "C" void kernel_launch(void* const* d_in, const int* in_sizes, int n_in,
                              void* d_out, int out_size) {
    const float* x    = (const float*)d_in[0];
    const float* cond = (const float*)d_in[1];
    const float* snr  = (const float*)d_in[2];
    const float* gw   = (const float*)d_in[3];
    const float* wgu  = (const float*)d_in[4];
    const float* wd   = (const float*)d_in[5];
    float* out = (float*)d_out;

    k0_init<<<1024, 256>>>(out, out_size);
    k1_gate<<<(T_TOK * 32 + 255) / 256, 256>>>(x, cond, snr, gw);
    k2_select<<<NE, 256>>>();
    k3_compact<<<TK / 256, 256>>>();

    dim3 g1(CAP / BM, (INTER + BN - 1) / BN, NE);
    k4_gemm1<<<g1, 256>>>(x, wgu);

    dim3 g2(CAP / BM, CDIM / BN, NE);
    k5_gemm2<<<g2, 256>>>(wd, out);
}

// round 3
// speedup vs baseline: 1.5014x; 1.5014x over previous
#include <cuda_runtime.h>
#include <cstdint>
#include <math.h>

// Problem constants
#define T_TOK 16384
#define TK    32768
#define NE    8
#define CDIM  1024
#define INTER 2730
#define N2    5460
#define CAP   2560
#define AST   2736   // padded activation row stride (16B-aligned: 2736*4 = 10944)
#define IP    2736   // padded weight row stride for gate/up halves

// ---------------- scratch (device globals; no allocations) ----------------
__device__ unsigned long long g_key[TK];
__device__ int   g_eid[TK];
__device__ float g_val[TK];
__device__ unsigned long long g_thresh[NE];
__device__ int   g_cnt[NE];
__device__ int   g_tok[NE][CAP];
__device__ float g_w[NE][CAP];

// tf32 hi/lo split buffers (padded tails so ss=0 cp.async addresses stay in-bounds)
__device__ float g_xh[(size_t)T_TOK * CDIM];
__device__ float g_xl[(size_t)T_TOK * CDIM];
__device__ float g_wgh[(size_t)NE * CDIM * IP + 64];
__device__ float g_wgl[(size_t)NE * CDIM * IP + 64];
__device__ float g_wuh[(size_t)NE * CDIM * IP + 64];
__device__ float g_wul[(size_t)NE * CDIM * IP + 64];
__device__ float g_wdh[(size_t)NE * INTER * CDIM + 8192];
__device__ float g_wdl[(size_t)NE * INTER * CDIM + 8192];
__device__ float g_acth[(size_t)NE * CAP * AST + 64];
__device__ float g_actl[(size_t)NE * CAP * AST + 64];

// ---------------- PTX helpers ----------------
__device__ __forceinline__ uint32_t cvt_tf32(float f) {
    uint32_t u; asm("cvt.rna.tf32.f32 %0, %1;" : "=r"(u) : "f"(f)); return u;
}
__device__ __forceinline__ uint32_t saddr(const void* p) {
    return (uint32_t)__cvta_generic_to_shared(p);
}
__device__ __forceinline__ void cp16(uint32_t d, const void* s) {
    asm volatile("cp.async.cg.shared.global [%0], [%1], 16;\n" :: "r"(d), "l"(s));
}
__device__ __forceinline__ void cp16z(uint32_t d, const void* s, int ss) {
    asm volatile("cp.async.cg.shared.global [%0], [%1], 16, %2;\n" :: "r"(d), "l"(s), "r"(ss));
}
__device__ __forceinline__ void cpcommit() { asm volatile("cp.async.commit_group;\n"); }
template<int N> __device__ __forceinline__ void cpwait() {
    asm volatile("cp.async.wait_group %0;\n" :: "n"(N));
}
__device__ __forceinline__ void mma8(float* c, const uint32_t* a, const uint32_t* b) {
    asm volatile(
        "mma.sync.aligned.m16n8k8.row.col.f32.tf32.tf32.f32 "
        "{%0,%1,%2,%3},{%4,%5,%6,%7},{%8,%9},{%0,%1,%2,%3};"
        : "+f"(c[0]), "+f"(c[1]), "+f"(c[2]), "+f"(c[3])
        : "r"(a[0]), "r"(a[1]), "r"(a[2]), "r"(a[3]), "r"(b[0]), "r"(b[1]));
}

// ---------------- kernel 0: init ----------------
__global__ void k0_init(float* out, int out_size) {
    int i = blockIdx.x * blockDim.x + threadIdx.x;
    int stride = gridDim.x * blockDim.x;
    for (int j = i; j < out_size; j += stride) out[j] = 0.0f;
    if (i < NE) g_cnt[i] = 0;
    for (int j = i; j < NE * CAP; j += stride) {
        ((int*)g_tok)[j] = 0;
        ((float*)g_w)[j] = 0.0f;
    }
}

// ---------------- split: v -> (tf32 hi, tf32 lo), aligned layouts -----------
__global__ void ksplit(const float* __restrict__ s, int n, int which) {
    float* h = (which == 0) ? g_xh : g_wdh;
    float* l = (which == 0) ? g_xl : g_wdl;
    int i = blockIdx.x * blockDim.x + threadIdx.x;
    int stride = gridDim.x * blockDim.x;
    for (int j = i * 4; j < n; j += stride * 4) {
        float4 v = *(const float4*)(s + j);
        float4 vh, vl;
        float* pv = (float*)&v; float* ph = (float*)&vh; float* pl = (float*)&vl;
#pragma unroll
        for (int q = 0; q < 4; ++q) {
            float hf = __uint_as_float(cvt_tf32(pv[q]));
            ph[q] = hf;
            pl[q] = __uint_as_float(cvt_tf32(pv[q] - hf));
        }
        *(float4*)(h + j) = vh;
        *(float4*)(l + j) = vl;
    }
}

// split gate_up_w [E][C][5460] -> gate/up arrays [E][C][IP] (padded, aligned)
__global__ void ksplit_gu(const float* __restrict__ s) {
    const int n = NE * CDIM * N2;
    int i = blockIdx.x * blockDim.x + threadIdx.x;
    int stride = gridDim.x * blockDim.x;
    for (int j = i * 4; j < n; j += stride * 4) {
        float4 v = *(const float4*)(s + j);
        float* pv = (float*)&v;
        int row = j / N2;           // e*CDIM + k  (float4 never straddles rows: N2 % 4 == 0)
        int col0 = j - row * N2;
#pragma unroll
        for (int q = 0; q < 4; ++q) {
            int col = col0 + q;
            float val = pv[q];
            float hf = __uint_as_float(cvt_tf32(val));
            float lf = __uint_as_float(cvt_tf32(val - hf));
            if (col < INTER) {
                size_t d = (size_t)row * IP + col;
                g_wgh[d] = hf; g_wgl[d] = lf;
            } else {
                size_t d = (size_t)row * IP + (col - INTER);
                g_wuh[d] = hf; g_wul[d] = lf;
            }
        }
    }
}

// ---------------- kernel 1: gating (one warp per token) ----------------
__global__ void k1_gate(const float* __restrict__ x, const float* __restrict__ cond,
                        const float* __restrict__ snr, const float* __restrict__ gw) {
    int warp = (blockIdx.x * blockDim.x + threadIdx.x) >> 5;
    int lane = threadIdx.x & 31;
    if (warp >= T_TOK) return;
    int t = warp;
    int b = t >> 12;

    float acc[NE];
#pragma unroll
    for (int e = 0; e < NE; ++e) acc[e] = 0.0f;

    const float* xr = x + (size_t)t * CDIM;
    const float* cr = cond + (size_t)b * CDIM;
    for (int d = lane; d < 2 * CDIM; d += 32) {
        float v = (d < CDIM) ? xr[d] : cr[d - CDIM];
        const float* wrow = gw + (size_t)d * NE;
#pragma unroll
        for (int e = 0; e < NE; ++e) acc[e] += v * wrow[e];
    }
#pragma unroll
    for (int e = 0; e < NE; ++e) {
#pragma unroll
        for (int o = 16; o > 0; o >>= 1)
            acc[e] += __shfl_xor_sync(0xFFFFFFFFu, acc[e], o);
    }

    if (lane == 0) {
        bool hn = snr[b] < 0.5f;
        float lg[NE];
#pragma unroll
        for (int e = 0; e < NE; ++e)
            lg[e] = (hn && e >= 2) ? -INFINITY : acc[e];

        float mx = lg[0];
#pragma unroll
        for (int e = 1; e < NE; ++e) mx = fmaxf(mx, lg[e]);
        float p[NE], s = 0.0f;
#pragma unroll
        for (int e = 0; e < NE; ++e) { p[e] = expf(lg[e] - mx); s += p[e]; }
        float inv = 1.0f / s;
#pragma unroll
        for (int e = 0; e < NE; ++e) p[e] *= inv;

        int i0 = 0; float p0 = p[0];
#pragma unroll
        for (int e = 1; e < NE; ++e) if (p[e] > p0) { p0 = p[e]; i0 = e; }
        int i1 = -1; float p1 = -1.0f;
#pragma unroll
        for (int e = 0; e < NE; ++e) if (e != i0 && p[e] > p1) { p1 = p[e]; i1 = e; }

        float denom = fmaxf(p0 + p1, 1e-12f);
        float w0 = p0 / denom, w1 = p1 / denom;

        int s0 = t * 2, s1 = t * 2 + 1;
        g_eid[s0] = i0; g_val[s0] = w0;
        g_key[s0] = ((unsigned long long)__float_as_uint(w0) << 32) |
                    (unsigned long long)(0xFFFFFFFFu - (unsigned)s0);
        g_eid[s1] = i1; g_val[s1] = w1;
        g_key[s1] = ((unsigned long long)__float_as_uint(w1) << 32) |
                    (unsigned long long)(0xFFFFFFFFu - (unsigned)s1);
    }
}

// ---------------- kernel 2: per-expert exact radix select ----------------
__global__ void k2_select() {
    int e = blockIdx.x;
    int tid = threadIdx.x;
    __shared__ int hist[256];
    __shared__ unsigned long long sh_prefix;
    __shared__ int sh_rem;
    __shared__ int sh_n;

    int cnt = 0;
    for (int s = tid; s < TK; s += 256) if (g_eid[s] == e) cnt++;
    if (tid == 0) sh_n = 0;
    __syncthreads();
    atomicAdd(&sh_n, cnt);
    __syncthreads();
    int n = sh_n;

    if (n <= CAP) {
        if (tid == 0) g_thresh[e] = 0ULL;
        return;
    }

    if (tid == 0) { sh_prefix = 0ULL; sh_rem = CAP; }
    __syncthreads();

    for (int p = 7; p >= 0; --p) {
        if (tid < 256) hist[tid] = 0;
        __syncthreads();
        unsigned long long prefix = sh_prefix;
        int shift_lo = p * 8;
        for (int s = tid; s < TK; s += 256) {
            if (g_eid[s] != e) continue;
            unsigned long long key = g_key[s];
            bool match = (p == 7) || (((key ^ prefix) >> ((p + 1) * 8)) == 0ULL);
            if (match)
                atomicAdd(&hist[(int)((key >> shift_lo) & 255ULL)], 1);
        }
        __syncthreads();
        if (tid == 0) {
            int rem = sh_rem;
            int cum = 0, d = 255;
            for (; d > 0; --d) { cum += hist[d]; if (cum >= rem) break; }
            if (cum < rem) cum += hist[0];
            sh_prefix |= ((unsigned long long)d) << shift_lo;
            sh_rem = rem - (cum - hist[d]);
        }
        __syncthreads();
    }
    if (tid == 0) g_thresh[e] = sh_prefix;
}

// ---------------- kernel 3: compaction ----------------
__global__ void k3_compact() {
    int s = blockIdx.x * blockDim.x + threadIdx.x;
    if (s >= TK) return;
    int e = g_eid[s];
    if (g_key[s] >= g_thresh[e]) {
        int pos = atomicAdd(&g_cnt[e], 1);
        if (pos < CAP) {
            g_tok[e][pos] = s >> 1;
            g_w[e][pos] = g_val[s];
        }
    }
}

// ---------------- kernel 4: gate_up GEMM (tf32x3) + SiLU*up, split store ---
__global__ __launch_bounds__(256) void k4_gemm1() {
    const int e = blockIdx.z, m0 = blockIdx.x * 128, n0 = blockIdx.y * 64;
    __shared__ float Ah[2][128][12], Al[2][128][12];
    __shared__ float Bh[2][2][8][72], Bl[2][2][8][72];

    const int tid = threadIdx.x, warp = tid >> 5, lane = tid & 31;
    const int wm = warp >> 1, wn = warp & 1;
    const int gID = lane >> 2, t4 = lane & 3;

    // A loader: thread -> (row, 16B chunk)
    const int rowA = tid >> 1, cA = (tid & 1) * 4;
    const int tokA = g_tok[e][m0 + rowA];
    const float* gxh = g_xh + (size_t)tokA * CDIM + cA;
    const float* gxl = g_xl + (size_t)tokA * CDIM + cA;
    const uint32_t dAh = saddr(&Ah[0][rowA][cA]);
    const uint32_t dAl = saddr(&Al[0][rowA][cA]);
    const uint32_t strA = 128 * 12 * 4;

    // B loader: threads [0,128) -> gate arrays, [128,256) -> up arrays
    const int gu = tid >> 7;
    const int tb = tid & 127;
    const int kkB = tb >> 4, nnB = (tb & 15) * 4;
    const int colb = n0 + nnB;
    int ssB = (INTER - colb) * 4; ssB = ssB < 0 ? 0 : (ssB > 16 ? 16 : ssB);
    const float* gBh = (gu ? g_wuh : g_wgh) + (size_t)e * CDIM * IP + (size_t)kkB * IP + colb;
    const float* gBl = (gu ? g_wul : g_wgl) + (size_t)e * CDIM * IP + (size_t)kkB * IP + colb;
    const uint32_t dBh = saddr(&Bh[0][gu][kkB][nnB]);
    const uint32_t dBl = saddr(&Bl[0][gu][kkB][nnB]);
    const uint32_t strB = 2 * 8 * 72 * 4;

    float acc[2][2][4][4] = {};   // [gu][mt][nt][q]

    auto load = [&](int it, int buf) {
        cp16(dAh + buf * strA, gxh + it * 8);
        cp16(dAl + buf * strA, gxl + it * 8);
        cp16z(dBh + buf * strB, gBh + (size_t)it * 8 * IP, ssB);
        cp16z(dBl + buf * strB, gBl + (size_t)it * 8 * IP, ssB);
        cpcommit();
    };

    load(0, 0);

#pragma unroll 1
    for (int it = 0; it < CDIM / 8; ++it) {
        if (it + 1 < CDIM / 8) { load(it + 1, (it + 1) & 1); cpwait<1>(); }
        else cpwait<0>();
        __syncthreads();

        const int buf = it & 1;
        uint32_t a_h[2][4], a_l[2][4];
#pragma unroll
        for (int mt = 0; mt < 2; ++mt) {
            int r = wm * 32 + mt * 16 + gID;
            a_h[mt][0] = __float_as_uint(Ah[buf][r][t4]);
            a_h[mt][1] = __float_as_uint(Ah[buf][r + 8][t4]);
            a_h[mt][2] = __float_as_uint(Ah[buf][r][t4 + 4]);
            a_h[mt][3] = __float_as_uint(Ah[buf][r + 8][t4 + 4]);
            a_l[mt][0] = __float_as_uint(Al[buf][r][t4]);
            a_l[mt][1] = __float_as_uint(Al[buf][r + 8][t4]);
            a_l[mt][2] = __float_as_uint(Al[buf][r][t4 + 4]);
            a_l[mt][3] = __float_as_uint(Al[buf][r + 8][t4 + 4]);
        }
#pragma unroll
        for (int g = 0; g < 2; ++g) {
            uint32_t b_h[4][2], b_l[4][2];
#pragma unroll
            for (int nt = 0; nt < 4; ++nt) {
                int c = wn * 32 + nt * 8 + gID;
                b_h[nt][0] = __float_as_uint(Bh[buf][g][t4][c]);
                b_h[nt][1] = __float_as_uint(Bh[buf][g][t4 + 4][c]);
                b_l[nt][0] = __float_as_uint(Bl[buf][g][t4][c]);
                b_l[nt][1] = __float_as_uint(Bl[buf][g][t4 + 4][c]);
            }
#pragma unroll
            for (int mt = 0; mt < 2; ++mt)
#pragma unroll
                for (int nt = 0; nt < 4; ++nt) {
                    mma8(acc[g][mt][nt], a_h[mt], b_h[nt]);
                    mma8(acc[g][mt][nt], a_h[mt], b_l[nt]);
                    mma8(acc[g][mt][nt], a_l[mt], b_h[nt]);
                }
        }
        __syncthreads();
    }

    // epilogue: silu(g)*u, split to tf32 hi/lo
    float* ph = g_acth + (size_t)e * CAP * AST;
    float* pl = g_actl + (size_t)e * CAP * AST;
#pragma unroll
    for (int mt = 0; mt < 2; ++mt)
#pragma unroll
        for (int nt = 0; nt < 4; ++nt) {
            int rbase = m0 + wm * 32 + mt * 16 + gID;
            int cbase = n0 + wn * 32 + nt * 8 + 2 * t4;
#pragma unroll
            for (int q = 0; q < 4; ++q) {
                int row = rbase + (q >> 1) * 8;
                int col = cbase + (q & 1);
                if (col < INTER) {
                    float gg = acc[0][mt][nt][q];
                    float uu = acc[1][mt][nt][q];
                    float a = __fdividef(gg, 1.0f + __expf(-gg)) * uu;
                    float hf = __uint_as_float(cvt_tf32(a));
                    ph[(size_t)row * AST + col] = hf;
                    pl[(size_t)row * AST + col] = __uint_as_float(cvt_tf32(a - hf));
                }
            }
        }
}

// ---------------- kernel 5: down GEMM (tf32x3) + scatter ----------------
__global__ __launch_bounds__(256) void k5_gemm2(float* __restrict__ out) {
    const int e = blockIdx.z, m0 = blockIdx.x * 128, n0 = blockIdx.y * 64;
    __shared__ float Ah[2][128][12], Al[2][128][12];
    __shared__ float Bh[2][8][72], Bl[2][8][72];

    const int tid = threadIdx.x, warp = tid >> 5, lane = tid & 31;
    const int wm = warp >> 1, wn = warp & 1;
    const int gID = lane >> 2, t4 = lane & 3;

    const int rowA = tid >> 1, cA = (tid & 1) * 4;
    const float* gah = g_acth + ((size_t)e * CAP + m0 + rowA) * AST + cA;
    const float* gal = g_actl + ((size_t)e * CAP + m0 + rowA) * AST + cA;
    const uint32_t dAh = saddr(&Ah[0][rowA][cA]);
    const uint32_t dAl = saddr(&Al[0][rowA][cA]);
    const uint32_t strA = 128 * 12 * 4;

    // B loader: threads [0,128) hi, [128,256) lo
    const int tb = tid & 127;
    const int kkB = tb >> 4, nnB = (tb & 15) * 4;
    const float* gB = ((tid < 128) ? g_wdh : g_wdl) +
                      (size_t)e * INTER * CDIM + (size_t)kkB * CDIM + n0 + nnB;
    float (*Bsel)[8][72] = (tid < 128) ? Bh : Bl;
    const uint32_t dB = saddr(&Bsel[0][kkB][nnB]);
    const uint32_t strB = 8 * 72 * 4;

    float acc[2][4][4] = {};

    auto load = [&](int it, int buf) {
        int colA = it * 8 + cA;
        int ssA = (INTER - colA) * 4; ssA = ssA < 0 ? 0 : (ssA > 16 ? 16 : ssA);
        cp16z(dAh + buf * strA, gah + it * 8, ssA);
        cp16z(dAl + buf * strA, gal + it * 8, ssA);
        int ssB = (it * 8 + kkB < INTER) ? 16 : 0;
        cp16z(dB + buf * strB, gB + (size_t)it * 8 * CDIM, ssB);
        cpcommit();
    };

    const int NIT = AST / 8;   // 342
    load(0, 0);

#pragma unroll 1
    for (int it = 0; it < NIT; ++it) {
        if (it + 1 < NIT) { load(it + 1, (it + 1) & 1); cpwait<1>(); }
        else cpwait<0>();
        __syncthreads();

        const int buf = it & 1;
        uint32_t a_h[2][4], a_l[2][4];
#pragma unroll
        for (int mt = 0; mt < 2; ++mt) {
            int r = wm * 32 + mt * 16 + gID;
            a_h[mt][0] = __float_as_uint(Ah[buf][r][t4]);
            a_h[mt][1] = __float_as_uint(Ah[buf][r + 8][t4]);
            a_h[mt][2] = __float_as_uint(Ah[buf][r][t4 + 4]);
            a_h[mt][3] = __float_as_uint(Ah[buf][r + 8][t4 + 4]);
            a_l[mt][0] = __float_as_uint(Al[buf][r][t4]);
            a_l[mt][1] = __float_as_uint(Al[buf][r + 8][t4]);
            a_l[mt][2] = __float_as_uint(Al[buf][r][t4 + 4]);
            a_l[mt][3] = __float_as_uint(Al[buf][r + 8][t4 + 4]);
        }
        uint32_t b_h[4][2], b_l[4][2];
#pragma unroll
        for (int nt = 0; nt < 4; ++nt) {
            int c = wn * 32 + nt * 8 + gID;
            b_h[nt][0] = __float_as_uint(Bh[buf][t4][c]);
            b_h[nt][1] = __float_as_uint(Bh[buf][t4 + 4][c]);
            b_l[nt][0] = __float_as_uint(Bl[buf][t4][c]);
            b_l[nt][1] = __float_as_uint(Bl[buf][t4 + 4][c]);
        }
#pragma unroll
        for (int mt = 0; mt < 2; ++mt)
#pragma unroll
            for (int nt = 0; nt < 4; ++nt) {
                mma8(acc[mt][nt], a_h[mt], b_h[nt]);
                mma8(acc[mt][nt], a_h[mt], b_l[nt]);
                mma8(acc[mt][nt], a_l[mt], b_h[nt]);
            }
        __syncthreads();
    }

    // epilogue: scale by routing weight, atomic scatter
#pragma unroll
    for (int mt = 0; mt < 2; ++mt)
#pragma unroll
        for (int rq = 0; rq < 2; ++rq) {
            int row = m0 + wm * 32 + mt * 16 + gID + rq * 8;
            float w = g_w[e][row];
            if (w == 0.0f) continue;
            int tok = g_tok[e][row];
            float* orow = out + (size_t)tok * CDIM;
#pragma unroll
            for (int nt = 0; nt < 4; ++nt) {
                int col = n0 + wn * 32 + nt * 8 + 2 * t4;
                atomicAdd(&orow[col],     acc[mt][nt][rq * 2 + 0] * w);
                atomicAdd(&orow[col + 1], acc[mt][nt][rq * 2 + 1] * w);
            }
        }
}

// ---------------- launch ----------------
extern "C" void kernel_launch(void* const* d_in, const int* in_sizes, int n_in,
                              void* d_out, int out_size) {
    const float* x    = (const float*)d_in[0];
    const float* cond = (const float*)d_in[1];
    const float* snr  = (const float*)d_in[2];
    const float* gw   = (const float*)d_in[3];
    const float* wgu  = (const float*)d_in[4];
    const float* wd   = (const float*)d_in[5];
    float* out = (float*)d_out;

    k0_init<<<1024, 256>>>(out, out_size);
    ksplit<<<2048, 256>>>(x,   T_TOK * CDIM, 0);
    ksplit_gu<<<2048, 256>>>(wgu);
    ksplit<<<2048, 256>>>(wd,  NE * INTER * CDIM, 1);
    k1_gate<<<(T_TOK * 32 + 255) / 256, 256>>>(x, cond, snr, gw);
    k2_select<<<NE, 256>>>();
    k3_compact<<<TK / 256, 256>>>();

    dim3 g1(CAP / 128, (INTER + 63) / 64, NE);
    k4_gemm1<<<g1, 256>>>();

    dim3 g2(CAP / 128, CDIM / 64, NE);
    k5_gemm2<<<g2, 256>>>(out);
}

// round 4
// speedup vs baseline: 2.1594x; 1.4383x over previous
#include <cuda_runtime.h>
#include <cuda_bf16.h>
#include <cstdint>
#include <math.h>

// Problem constants
#define T_TOK 16384
#define TK    32768
#define NE    8
#define CDIM  1024
#define INTER 2730
#define N2    5460
#define CAP   2560
#define AST   2736   // padded activation k-stride (halves; 5472B, 16B aligned)
#define NP    2752   // padded n-rows for gate/up transposed weights
#define KP    2736   // padded k-stride for transposed down weights

typedef unsigned short ushort_t;

// ---------------- scratch (device globals; zero-initialized) ----------------
__device__ unsigned long long g_key[TK];
__device__ int   g_eid[TK];
__device__ float g_val[TK];
__device__ unsigned long long g_thresh[NE];
__device__ int   g_cnt[NE];
__device__ int   g_tok[NE][CAP];
__device__ float g_w[NE][CAP];

// bf16 hi/lo split buffers
__device__ ushort_t g_xh[(size_t)T_TOK * CDIM];
__device__ ushort_t g_xl[(size_t)T_TOK * CDIM];
__device__ ushort_t g_wgh[(size_t)NE * NP * CDIM];   // gate, transposed [e][n][k]
__device__ ushort_t g_wgl[(size_t)NE * NP * CDIM];
__device__ ushort_t g_wuh[(size_t)NE * NP * CDIM];   // up
__device__ ushort_t g_wul[(size_t)NE * NP * CDIM];
__device__ ushort_t g_wdh[(size_t)NE * CDIM * KP];   // down, transposed [e][n][k]
__device__ ushort_t g_wdl[(size_t)NE * CDIM * KP];
__device__ ushort_t g_acth[(size_t)NE * CAP * AST];
__device__ ushort_t g_actl[(size_t)NE * CAP * AST];

// ---------------- helpers ----------------
__device__ __forceinline__ ushort_t bf16h(float f) {
    __nv_bfloat16 b = __float2bfloat16(f);
    return *(ushort_t*)&b;
}
__device__ __forceinline__ float bf2f(ushort_t u) {
    __nv_bfloat16 b = *(__nv_bfloat16*)&u;
    return __bfloat162float(b);
}
__device__ __forceinline__ uint32_t saddr(const void* p) {
    return (uint32_t)__cvta_generic_to_shared(p);
}
__device__ __forceinline__ void cp16(uint32_t d, const void* s) {
    asm volatile("cp.async.cg.shared.global [%0], [%1], 16;\n" :: "r"(d), "l"(s));
}
__device__ __forceinline__ void cpcommit() { asm volatile("cp.async.commit_group;\n"); }
template<int N> __device__ __forceinline__ void cpwait() {
    asm volatile("cp.async.wait_group %0;\n" :: "n"(N));
}
__device__ __forceinline__ void mma16(float* c, const uint32_t* a, const uint32_t* b) {
    asm volatile(
        "mma.sync.aligned.m16n8k16.row.col.f32.bf16.bf16.f32 "
        "{%0,%1,%2,%3},{%4,%5,%6,%7},{%8,%9},{%0,%1,%2,%3};"
        : "+f"(c[0]), "+f"(c[1]), "+f"(c[2]), "+f"(c[3])
        : "r"(a[0]), "r"(a[1]), "r"(a[2]), "r"(a[3]), "r"(b[0]), "r"(b[1]));
}

// ---------------- kernel 0: init ----------------
__global__ void k0_init(float* out, int out_size) {
    int i = blockIdx.x * blockDim.x + threadIdx.x;
    int stride = gridDim.x * blockDim.x;
    for (int j = i; j < out_size; j += stride) out[j] = 0.0f;
    if (i < NE) g_cnt[i] = 0;
    for (int j = i; j < NE * CAP; j += stride) {
        ((int*)g_tok)[j] = 0;
        ((float*)g_w)[j] = 0.0f;
    }
}

// ---------------- split x -> bf16 hi/lo ----------------
__global__ void ksplit_x(const float* __restrict__ s) {
    const int n = T_TOK * CDIM;
    int i = blockIdx.x * blockDim.x + threadIdx.x;
    int stride = gridDim.x * blockDim.x;
    for (int j = i * 4; j < n; j += stride * 4) {
        float4 v = *(const float4*)(s + j);
        float* pv = (float*)&v;
        uint32_t h[2], l[2];
#pragma unroll
        for (int p = 0; p < 2; ++p) {
            ushort_t h0 = bf16h(pv[2*p]);
            ushort_t h1 = bf16h(pv[2*p+1]);
            ushort_t l0 = bf16h(pv[2*p]   - bf2f(h0));
            ushort_t l1 = bf16h(pv[2*p+1] - bf2f(h1));
            h[p] = (uint32_t)h0 | ((uint32_t)h1 << 16);
            l[p] = (uint32_t)l0 | ((uint32_t)l1 << 16);
        }
        *(uint32_t*)(g_xh + j)     = h[0];
        *(uint32_t*)(g_xh + j + 2) = h[1];
        *(uint32_t*)(g_xl + j)     = l[0];
        *(uint32_t*)(g_xl + j + 2) = l[1];
    }
}

// ---------------- split + transpose gate_up_w [e][k][5460] -> [e][n][k] -----
__global__ void ksplit_gu_t(const float* __restrict__ s) {
    __shared__ float tile[32][33];
    const int e = blockIdx.z;
    const int n0 = blockIdx.x * 32, k0 = blockIdx.y * 32;
    const int tx = threadIdx.x, ty = threadIdx.y;   // 32x8
    for (int i = ty; i < 32; i += 8) {
        int n = n0 + tx, k = k0 + i;
        tile[i][tx] = (n < N2) ? s[((size_t)e * CDIM + k) * N2 + n] : 0.0f;
    }
    __syncthreads();
    for (int i = ty; i < 32; i += 8) {
        int n = n0 + i, k = k0 + tx;
        if (n >= N2) continue;
        float v = tile[tx][i];
        ushort_t h = bf16h(v);
        ushort_t l = bf16h(v - bf2f(h));
        if (n < INTER) {
            size_t d = ((size_t)e * NP + n) * CDIM + k;
            g_wgh[d] = h; g_wgl[d] = l;
        } else {
            size_t d = ((size_t)e * NP + (n - INTER)) * CDIM + k;
            g_wuh[d] = h; g_wul[d] = l;
        }
    }
}

// ---------------- split + transpose down_w [e][k=INTER][n=CDIM] -> [e][n][k]
__global__ void ksplit_dw_t(const float* __restrict__ s) {
    __shared__ float tile[32][33];
    const int e = blockIdx.z;
    const int n0 = blockIdx.x * 32, k0 = blockIdx.y * 32;
    const int tx = threadIdx.x, ty = threadIdx.y;
    for (int i = ty; i < 32; i += 8) {
        int k = k0 + i;
        tile[i][tx] = (k < INTER) ? s[((size_t)e * INTER + k) * CDIM + n0 + tx] : 0.0f;
    }
    __syncthreads();
    for (int i = ty; i < 32; i += 8) {
        int n = n0 + i, k = k0 + tx;
        if (k >= INTER) continue;
        float v = tile[tx][i];
        ushort_t h = bf16h(v);
        ushort_t l = bf16h(v - bf2f(h));
        size_t d = ((size_t)e * CDIM + n) * KP + k;
        g_wdh[d] = h; g_wdl[d] = l;
    }
}

// ---------------- kernel 1: gating (one warp per token) ----------------
__global__ void k1_gate(const float* __restrict__ x, const float* __restrict__ cond,
                        const float* __restrict__ snr, const float* __restrict__ gw) {
    int warp = (blockIdx.x * blockDim.x + threadIdx.x) >> 5;
    int lane = threadIdx.x & 31;
    if (warp >= T_TOK) return;
    int t = warp;
    int b = t >> 12;

    float acc[NE];
#pragma unroll
    for (int e = 0; e < NE; ++e) acc[e] = 0.0f;

    const float* xr = x + (size_t)t * CDIM;
    const float* cr = cond + (size_t)b * CDIM;
    for (int d = lane; d < 2 * CDIM; d += 32) {
        float v = (d < CDIM) ? xr[d] : cr[d - CDIM];
        const float* wrow = gw + (size_t)d * NE;
#pragma unroll
        for (int e = 0; e < NE; ++e) acc[e] += v * wrow[e];
    }
#pragma unroll
    for (int e = 0; e < NE; ++e) {
#pragma unroll
        for (int o = 16; o > 0; o >>= 1)
            acc[e] += __shfl_xor_sync(0xFFFFFFFFu, acc[e], o);
    }

    if (lane == 0) {
        bool hn = snr[b] < 0.5f;
        float lg[NE];
#pragma unroll
        for (int e = 0; e < NE; ++e)
            lg[e] = (hn && e >= 2) ? -INFINITY : acc[e];

        float mx = lg[0];
#pragma unroll
        for (int e = 1; e < NE; ++e) mx = fmaxf(mx, lg[e]);
        float p[NE], s = 0.0f;
#pragma unroll
        for (int e = 0; e < NE; ++e) { p[e] = expf(lg[e] - mx); s += p[e]; }
        float inv = 1.0f / s;
#pragma unroll
        for (int e = 0; e < NE; ++e) p[e] *= inv;

        int i0 = 0; float p0 = p[0];
#pragma unroll
        for (int e = 1; e < NE; ++e) if (p[e] > p0) { p0 = p[e]; i0 = e; }
        int i1 = -1; float p1 = -1.0f;
#pragma unroll
        for (int e = 0; e < NE; ++e) if (e != i0 && p[e] > p1) { p1 = p[e]; i1 = e; }

        float denom = fmaxf(p0 + p1, 1e-12f);
        float w0 = p0 / denom, w1 = p1 / denom;

        int s0 = t * 2, s1 = t * 2 + 1;
        g_eid[s0] = i0; g_val[s0] = w0;
        g_key[s0] = ((unsigned long long)__float_as_uint(w0) << 32) |
                    (unsigned long long)(0xFFFFFFFFu - (unsigned)s0);
        g_eid[s1] = i1; g_val[s1] = w1;
        g_key[s1] = ((unsigned long long)__float_as_uint(w1) << 32) |
                    (unsigned long long)(0xFFFFFFFFu - (unsigned)s1);
    }
}

// ---------------- kernel 2: per-expert exact radix select ----------------
__global__ void k2_select() {
    int e = blockIdx.x;
    int tid = threadIdx.x;
    __shared__ int hist[256];
    __shared__ unsigned long long sh_prefix;
    __shared__ int sh_rem;
    __shared__ int sh_n;

    int cnt = 0;
    for (int s = tid; s < TK; s += 256) if (g_eid[s] == e) cnt++;
    if (tid == 0) sh_n = 0;
    __syncthreads();
    atomicAdd(&sh_n, cnt);
    __syncthreads();
    int n = sh_n;

    if (n <= CAP) {
        if (tid == 0) g_thresh[e] = 0ULL;
        return;
    }

    if (tid == 0) { sh_prefix = 0ULL; sh_rem = CAP; }
    __syncthreads();

    for (int p = 7; p >= 0; --p) {
        if (tid < 256) hist[tid] = 0;
        __syncthreads();
        unsigned long long prefix = sh_prefix;
        int shift_lo = p * 8;
        for (int s = tid; s < TK; s += 256) {
            if (g_eid[s] != e) continue;
            unsigned long long key = g_key[s];
            bool match = (p == 7) || (((key ^ prefix) >> ((p + 1) * 8)) == 0ULL);
            if (match)
                atomicAdd(&hist[(int)((key >> shift_lo) & 255ULL)], 1);
        }
        __syncthreads();
        if (tid == 0) {
            int rem = sh_rem;
            int cum = 0, d = 255;
            for (; d > 0; --d) { cum += hist[d]; if (cum >= rem) break; }
            if (cum < rem) cum += hist[0];
            sh_prefix |= ((unsigned long long)d) << shift_lo;
            sh_rem = rem - (cum - hist[d]);
        }
        __syncthreads();
    }
    if (tid == 0) g_thresh[e] = sh_prefix;
}

// ---------------- kernel 3: compaction ----------------
__global__ void k3_compact() {
    int s = blockIdx.x * blockDim.x + threadIdx.x;
    if (s >= TK) return;
    int e = g_eid[s];
    if (g_key[s] >= g_thresh[e]) {
        int pos = atomicAdd(&g_cnt[e], 1);
        if (pos < CAP) {
            g_tok[e][pos] = s >> 1;
            g_w[e][pos] = g_val[s];
        }
    }
}

// ---------------- kernel 4: gate_up GEMM (bf16x3) + SiLU*up ----------------
__global__ __launch_bounds__(256) void k4_gemm1() {
    const int e = blockIdx.z, m0 = blockIdx.x * 128, n0 = blockIdx.y * 64;
    __shared__ ushort_t Ah[2][128][24], Al[2][128][24];
    __shared__ ushort_t Bh[2][2][64][24], Bl[2][2][64][24];

    const int tid = threadIdx.x, warp = tid >> 5, lane = tid & 31;
    const int wm = warp >> 1, wn = warp & 1;
    const int gID = lane >> 2, t4 = lane & 3;

    // A loader: tid -> (row, 8-half chunk)
    const int rowA = tid >> 1, chA = (tid & 1) * 8;
    const int tokA = g_tok[e][m0 + rowA];
    const ushort_t* gxh = g_xh + (size_t)tokA * CDIM + chA;
    const ushort_t* gxl = g_xl + (size_t)tokA * CDIM + chA;

    // B loader: tid>>7 selects gate/up arrays; within 128: row (0..63), chunk
    const int gu = tid >> 7;
    const int r7 = tid & 127;
    const int rowB = r7 >> 1, chB = (r7 & 1) * 8;
    const ushort_t* gBh = (gu ? g_wuh : g_wgh) + ((size_t)e * NP + n0 + rowB) * CDIM + chB;
    const ushort_t* gBl = (gu ? g_wul : g_wgl) + ((size_t)e * NP + n0 + rowB) * CDIM + chB;

    float acc[2][2][4][4] = {};   // [gu][mt][nt][q]

    auto load = [&](int it, int buf) {
        cp16(saddr(&Ah[buf][rowA][chA]), gxh + it * 16);
        cp16(saddr(&Al[buf][rowA][chA]), gxl + it * 16);
        cp16(saddr(&Bh[buf][gu][rowB][chB]), gBh + it * 16);
        cp16(saddr(&Bl[buf][gu][rowB][chB]), gBl + it * 16);
        cpcommit();
    };

    load(0, 0);

#pragma unroll 1
    for (int it = 0; it < CDIM / 16; ++it) {
        if (it + 1 < CDIM / 16) { load(it + 1, (it + 1) & 1); cpwait<1>(); }
        else cpwait<0>();
        __syncthreads();

        const int buf = it & 1;
        uint32_t a_h[2][4], a_l[2][4];
#pragma unroll
        for (int mt = 0; mt < 2; ++mt) {
            int r = wm * 32 + mt * 16 + gID;
            a_h[mt][0] = *(uint32_t*)&Ah[buf][r][2 * t4];
            a_h[mt][1] = *(uint32_t*)&Ah[buf][r + 8][2 * t4];
            a_h[mt][2] = *(uint32_t*)&Ah[buf][r][2 * t4 + 8];
            a_h[mt][3] = *(uint32_t*)&Ah[buf][r + 8][2 * t4 + 8];
            a_l[mt][0] = *(uint32_t*)&Al[buf][r][2 * t4];
            a_l[mt][1] = *(uint32_t*)&Al[buf][r + 8][2 * t4];
            a_l[mt][2] = *(uint32_t*)&Al[buf][r][2 * t4 + 8];
            a_l[mt][3] = *(uint32_t*)&Al[buf][r + 8][2 * t4 + 8];
        }
#pragma unroll
        for (int g = 0; g < 2; ++g) {
            uint32_t b_h[4][2], b_l[4][2];
#pragma unroll
            for (int nt = 0; nt < 4; ++nt) {
                int c = wn * 32 + nt * 8 + gID;
                b_h[nt][0] = *(uint32_t*)&Bh[buf][g][c][2 * t4];
                b_h[nt][1] = *(uint32_t*)&Bh[buf][g][c][2 * t4 + 8];
                b_l[nt][0] = *(uint32_t*)&Bl[buf][g][c][2 * t4];
                b_l[nt][1] = *(uint32_t*)&Bl[buf][g][c][2 * t4 + 8];
            }
#pragma unroll
            for (int mt = 0; mt < 2; ++mt)
#pragma unroll
                for (int nt = 0; nt < 4; ++nt) {
                    mma16(acc[g][mt][nt], a_h[mt], b_h[nt]);
                    mma16(acc[g][mt][nt], a_h[mt], b_l[nt]);
                    mma16(acc[g][mt][nt], a_l[mt], b_h[nt]);
                }
        }
        __syncthreads();
    }

    // epilogue: silu(g)*u, split to bf16 hi/lo, packed pair writes
    ushort_t* ph = g_acth + (size_t)e * CAP * AST;
    ushort_t* pl = g_actl + (size_t)e * CAP * AST;
#pragma unroll
    for (int mt = 0; mt < 2; ++mt)
#pragma unroll
        for (int nt = 0; nt < 4; ++nt) {
            int rbase = m0 + wm * 32 + mt * 16 + gID;
            int col = n0 + wn * 32 + nt * 8 + 2 * t4;
            if (col >= INTER) continue;
#pragma unroll
            for (int rq = 0; rq < 2; ++rq) {
                int row = rbase + rq * 8;
                float g0 = acc[0][mt][nt][rq * 2],     u0 = acc[1][mt][nt][rq * 2];
                float g1 = acc[0][mt][nt][rq * 2 + 1], u1 = acc[1][mt][nt][rq * 2 + 1];
                float a0 = __fdividef(g0, 1.0f + __expf(-g0)) * u0;
                float a1 = __fdividef(g1, 1.0f + __expf(-g1)) * u1;
                ushort_t h0 = bf16h(a0), h1 = bf16h(a1);
                ushort_t l0 = bf16h(a0 - bf2f(h0)), l1 = bf16h(a1 - bf2f(h1));
                *(uint32_t*)(ph + (size_t)row * AST + col) = (uint32_t)h0 | ((uint32_t)h1 << 16);
                *(uint32_t*)(pl + (size_t)row * AST + col) = (uint32_t)l0 | ((uint32_t)l1 << 16);
            }
        }
}

// ---------------- kernel 5: down GEMM (bf16x3) + scatter ----------------
__global__ __launch_bounds__(256) void k5_gemm2(float* __restrict__ out) {
    const int e = blockIdx.z, m0 = blockIdx.x * 128, n0 = blockIdx.y * 64;
    __shared__ ushort_t Ah[2][128][24], Al[2][128][24];
    __shared__ ushort_t Bh[2][64][24], Bl[2][64][24];

    const int tid = threadIdx.x, warp = tid >> 5, lane = tid & 31;
    const int wm = warp >> 1, wn = warp & 1;
    const int gID = lane >> 2, t4 = lane & 3;

    const int rowA = tid >> 1, chA = (tid & 1) * 8;
    const ushort_t* gah = g_acth + ((size_t)e * CAP + m0 + rowA) * AST + chA;
    const ushort_t* gal = g_actl + ((size_t)e * CAP + m0 + rowA) * AST + chA;

    const int r7 = tid & 127;
    const int rowB = r7 >> 1, chB = (r7 & 1) * 8;
    const ushort_t* gB = ((tid < 128) ? g_wdh : g_wdl) +
                         ((size_t)e * CDIM + n0 + rowB) * KP + chB;
    ushort_t (*Bsel)[64][24] = (tid < 128) ? Bh : Bl;

    float acc[2][4][4] = {};

    auto load = [&](int it, int buf) {
        cp16(saddr(&Ah[buf][rowA][chA]), gah + it * 16);
        cp16(saddr(&Al[buf][rowA][chA]), gal + it * 16);
        cp16(saddr(&Bsel[buf][rowB][chB]), gB + it * 16);
        cpcommit();
    };

    const int NIT = KP / 16;   // 171
    load(0, 0);

#pragma unroll 1
    for (int it = 0; it < NIT; ++it) {
        if (it + 1 < NIT) { load(it + 1, (it + 1) & 1); cpwait<1>(); }
        else cpwait<0>();
        __syncthreads();

        const int buf = it & 1;
        uint32_t a_h[2][4], a_l[2][4];
#pragma unroll
        for (int mt = 0; mt < 2; ++mt) {
            int r = wm * 32 + mt * 16 + gID;
            a_h[mt][0] = *(uint32_t*)&Ah[buf][r][2 * t4];
            a_h[mt][1] = *(uint32_t*)&Ah[buf][r + 8][2 * t4];
            a_h[mt][2] = *(uint32_t*)&Ah[buf][r][2 * t4 + 8];
            a_h[mt][3] = *(uint32_t*)&Ah[buf][r + 8][2 * t4 + 8];
            a_l[mt][0] = *(uint32_t*)&Al[buf][r][2 * t4];
            a_l[mt][1] = *(uint32_t*)&Al[buf][r + 8][2 * t4];
            a_l[mt][2] = *(uint32_t*)&Al[buf][r][2 * t4 + 8];
            a_l[mt][3] = *(uint32_t*)&Al[buf][r + 8][2 * t4 + 8];
        }
        uint32_t b_h[4][2], b_l[4][2];
#pragma unroll
        for (int nt = 0; nt < 4; ++nt) {
            int c = wn * 32 + nt * 8 + gID;
            b_h[nt][0] = *(uint32_t*)&Bh[buf][c][2 * t4];
            b_h[nt][1] = *(uint32_t*)&Bh[buf][c][2 * t4 + 8];
            b_l[nt][0] = *(uint32_t*)&Bl[buf][c][2 * t4];
            b_l[nt][1] = *(uint32_t*)&Bl[buf][c][2 * t4 + 8];
        }
#pragma unroll
        for (int mt = 0; mt < 2; ++mt)
#pragma unroll
            for (int nt = 0; nt < 4; ++nt) {
                mma16(acc[mt][nt], a_h[mt], b_h[nt]);
                mma16(acc[mt][nt], a_h[mt], b_l[nt]);
                mma16(acc[mt][nt], a_l[mt], b_h[nt]);
            }
        __syncthreads();
    }

    // epilogue: scale by routing weight, atomic scatter
#pragma unroll
    for (int mt = 0; mt < 2; ++mt)
#pragma unroll
        for (int rq = 0; rq < 2; ++rq) {
            int row = m0 + wm * 32 + mt * 16 + gID + rq * 8;
            float w = g_w[e][row];
            if (w == 0.0f) continue;
            int tok = g_tok[e][row];
            float* orow = out + (size_t)tok * CDIM;
#pragma unroll
            for (int nt = 0; nt < 4; ++nt) {
                int col = n0 + wn * 32 + nt * 8 + 2 * t4;
                atomicAdd(&orow[col],     acc[mt][nt][rq * 2 + 0] * w);
                atomicAdd(&orow[col + 1], acc[mt][nt][rq * 2 + 1] * w);
            }
        }
}

// ---------------- launch ----------------
extern "C" void kernel_launch(void* const* d_in, const int* in_sizes, int n_in,
                              void* d_out, int out_size) {
    const float* x    = (const float*)d_in[0];
    const float* cond = (const float*)d_in[1];
    const float* snr  = (const float*)d_in[2];
    const float* gw   = (const float*)d_in[3];
    const float* wgu  = (const float*)d_in[4];
    const float* wd   = (const float*)d_in[5];
    float* out = (float*)d_out;

    k0_init<<<1024, 256>>>(out, out_size);
    ksplit_x<<<2048, 256>>>(x);
    {
        dim3 b(32, 8);
        dim3 g1((N2 + 31) / 32, CDIM / 32, NE);       // 171 x 32 x 8
        ksplit_gu_t<<<g1, b>>>(wgu);
        dim3 g2(CDIM / 32, (INTER + 31) / 32, NE);    // 32 x 86 x 8
        ksplit_dw_t<<<g2, b>>>(wd);
    }
    k1_gate<<<(T_TOK * 32 + 255) / 256, 256>>>(x, cond, snr, gw);
    k2_select<<<NE, 256>>>();
    k3_compact<<<TK / 256, 256>>>();

    dim3 gg1(CAP / 128, (INTER + 63) / 64, NE);
    k4_gemm1<<<gg1, 256>>>();

    dim3 gg2(CAP / 128, CDIM / 64, NE);
    k5_gemm2<<<gg2, 256>>>(out);
}

// round 6
// speedup vs baseline: 2.6454x; 1.2251x over previous
#include <cuda_runtime.h>
#include <cuda_fp16.h>
#include <cstdint>
#include <math.h>

// Problem constants
#define T_TOK 16384
#define TK    32768
#define NE    8
#define CDIM  1024
#define INTER 2730
#define N2    5460
#define CAP   2560
#define AST   2752   // activation k-stride (zero tail)
#define NP    2752   // padded n-rows for gate/up transposed weights
#define KP    2752   // padded k-stride for transposed down weights

typedef unsigned short ushort_t;

// ---------------- scratch (device globals; zero-initialized) ----------------
__device__ unsigned long long g_key[TK];
__device__ int   g_eid[TK];
__device__ float g_val[TK];
__device__ unsigned long long g_thresh[NE];
__device__ int   g_cnt[NE];
__device__ int   g_tok[NE][CAP];
__device__ float g_w[NE][CAP];

// fp16 buffers: x and activations split hi/lo, weights single copy
__device__ ushort_t g_xh[(size_t)T_TOK * CDIM];
__device__ ushort_t g_xl[(size_t)T_TOK * CDIM];
__device__ ushort_t g_wg[(size_t)NE * NP * CDIM];    // gate, [e][n][k]
__device__ ushort_t g_wu[(size_t)NE * NP * CDIM];    // up,   [e][n][k]
__device__ ushort_t g_wd[(size_t)NE * CDIM * KP];    // down, [e][n][k]
__device__ ushort_t g_acth[(size_t)NE * CAP * AST];
__device__ ushort_t g_actl[(size_t)NE * CAP * AST];

// ---------------- helpers ----------------
__device__ __forceinline__ ushort_t f2h(float f) {
    __half h = __float2half_rn(f);
    return *(ushort_t*)&h;
}
__device__ __forceinline__ float h2f(ushort_t u) {
    __half h = *(__half*)&u;
    return __half2float(h);
}
__device__ __forceinline__ uint32_t saddr(const void* p) {
    return (uint32_t)__cvta_generic_to_shared(p);
}
__device__ __forceinline__ void cp16(uint32_t d, const void* s) {
    asm volatile("cp.async.cg.shared.global [%0], [%1], 16;\n" :: "r"(d), "l"(s));
}
__device__ __forceinline__ void cpcommit() { asm volatile("cp.async.commit_group;\n"); }
template<int N> __device__ __forceinline__ void cpwait() {
    asm volatile("cp.async.wait_group %0;\n" :: "n"(N));
}
__device__ __forceinline__ void mma16(float* c, const uint32_t* a, const uint32_t* b) {
    asm volatile(
        "mma.sync.aligned.m16n8k16.row.col.f32.f16.f16.f32 "
        "{%0,%1,%2,%3},{%4,%5,%6,%7},{%8,%9},{%0,%1,%2,%3};"
        : "+f"(c[0]), "+f"(c[1]), "+f"(c[2]), "+f"(c[3])
        : "r"(a[0]), "r"(a[1]), "r"(a[2]), "r"(a[3]), "r"(b[0]), "r"(b[1]));
}

// ---------------- kernel 0: init ----------------
__global__ void k0_init(float* out, int out_size) {
    int i = blockIdx.x * blockDim.x + threadIdx.x;
    int stride = gridDim.x * blockDim.x;
    for (int j = i; j < out_size; j += stride) out[j] = 0.0f;
    if (i < NE) g_cnt[i] = 0;
    for (int j = i; j < NE * CAP; j += stride) {
        ((int*)g_tok)[j] = 0;
        ((float*)g_w)[j] = 0.0f;
    }
}

// ---------------- split x -> fp16 hi/lo ----------------
__global__ void ksplit_x(const float* __restrict__ s) {
    const int n = T_TOK * CDIM;
    int i = blockIdx.x * blockDim.x + threadIdx.x;
    int stride = gridDim.x * blockDim.x;
    for (int j = i * 4; j < n; j += stride * 4) {
        float4 v = *(const float4*)(s + j);
        float* pv = (float*)&v;
        uint32_t h[2], l[2];
#pragma unroll
        for (int p = 0; p < 2; ++p) {
            ushort_t h0 = f2h(pv[2*p]);
            ushort_t h1 = f2h(pv[2*p+1]);
            ushort_t l0 = f2h(pv[2*p]   - h2f(h0));
            ushort_t l1 = f2h(pv[2*p+1] - h2f(h1));
            h[p] = (uint32_t)h0 | ((uint32_t)h1 << 16);
            l[p] = (uint32_t)l0 | ((uint32_t)l1 << 16);
        }
        *(uint32_t*)(g_xh + j)     = h[0];
        *(uint32_t*)(g_xh + j + 2) = h[1];
        *(uint32_t*)(g_xl + j)     = l[0];
        *(uint32_t*)(g_xl + j + 2) = l[1];
    }
}

// ---------------- transpose gate_up_w [e][k][5460] -> fp16 [e][n][k] --------
__global__ void ksplit_gu_t(const float* __restrict__ s) {
    __shared__ float tile[32][33];
    const int e = blockIdx.z;
    const int n0 = blockIdx.x * 32, k0 = blockIdx.y * 32;
    const int tx = threadIdx.x, ty = threadIdx.y;
    for (int i = ty; i < 32; i += 8) {
        int n = n0 + tx, k = k0 + i;
        tile[i][tx] = (n < N2) ? s[((size_t)e * CDIM + k) * N2 + n] : 0.0f;
    }
    __syncthreads();
    for (int i = ty; i < 32; i += 8) {
        int n = n0 + i, k = k0 + tx;
        if (n >= N2) continue;
        ushort_t h = f2h(tile[tx][i]);
        if (n < INTER) {
            g_wg[((size_t)e * NP + n) * CDIM + k] = h;
        } else {
            g_wu[((size_t)e * NP + (n - INTER)) * CDIM + k] = h;
        }
    }
}

// ---------------- transpose down_w [e][k=INTER][n=CDIM] -> fp16 [e][n][k] ---
__global__ void ksplit_dw_t(const float* __restrict__ s) {
    __shared__ float tile[32][33];
    const int e = blockIdx.z;
    const int n0 = blockIdx.x * 32, k0 = blockIdx.y * 32;
    const int tx = threadIdx.x, ty = threadIdx.y;
    for (int i = ty; i < 32; i += 8) {
        int k = k0 + i;
        tile[i][tx] = (k < INTER) ? s[((size_t)e * INTER + k) * CDIM + n0 + tx] : 0.0f;
    }
    __syncthreads();
    for (int i = ty; i < 32; i += 8) {
        int n = n0 + i, k = k0 + tx;
        if (k >= INTER) continue;
        g_wd[((size_t)e * CDIM + n) * KP + k] = f2h(tile[tx][i]);
    }
}

// ---------------- kernel 1: gating (one warp per token) ----------------
__global__ void k1_gate(const float* __restrict__ x, const float* __restrict__ cond,
                        const float* __restrict__ snr, const float* __restrict__ gw) {
    int warp = (blockIdx.x * blockDim.x + threadIdx.x) >> 5;
    int lane = threadIdx.x & 31;
    if (warp >= T_TOK) return;
    int t = warp;
    int b = t >> 12;

    float acc[NE];
#pragma unroll
    for (int e = 0; e < NE; ++e) acc[e] = 0.0f;

    const float* xr = x + (size_t)t * CDIM;
    const float* cr = cond + (size_t)b * CDIM;
    for (int d = lane; d < 2 * CDIM; d += 32) {
        float v = (d < CDIM) ? xr[d] : cr[d - CDIM];
        const float* wrow = gw + (size_t)d * NE;
#pragma unroll
        for (int e = 0; e < NE; ++e) acc[e] += v * wrow[e];
    }
#pragma unroll
    for (int e = 0; e < NE; ++e) {
#pragma unroll
        for (int o = 16; o > 0; o >>= 1)
            acc[e] += __shfl_xor_sync(0xFFFFFFFFu, acc[e], o);
    }

    if (lane == 0) {
        bool hn = snr[b] < 0.5f;
        float lg[NE];
#pragma unroll
        for (int e = 0; e < NE; ++e)
            lg[e] = (hn && e >= 2) ? -INFINITY : acc[e];

        float mx = lg[0];
#pragma unroll
        for (int e = 1; e < NE; ++e) mx = fmaxf(mx, lg[e]);
        float p[NE], s = 0.0f;
#pragma unroll
        for (int e = 0; e < NE; ++e) { p[e] = expf(lg[e] - mx); s += p[e]; }
        float inv = 1.0f / s;
#pragma unroll
        for (int e = 0; e < NE; ++e) p[e] *= inv;

        int i0 = 0; float p0 = p[0];
#pragma unroll
        for (int e = 1; e < NE; ++e) if (p[e] > p0) { p0 = p[e]; i0 = e; }
        int i1 = -1; float p1 = -1.0f;
#pragma unroll
        for (int e = 0; e < NE; ++e) if (e != i0 && p[e] > p1) { p1 = p[e]; i1 = e; }

        float denom = fmaxf(p0 + p1, 1e-12f);
        float w0 = p0 / denom, w1 = p1 / denom;

        int s0 = t * 2, s1 = t * 2 + 1;
        g_eid[s0] = i0; g_val[s0] = w0;
        g_key[s0] = ((unsigned long long)__float_as_uint(w0) << 32) |
                    (unsigned long long)(0xFFFFFFFFu - (unsigned)s0);
        g_eid[s1] = i1; g_val[s1] = w1;
        g_key[s1] = ((unsigned long long)__float_as_uint(w1) << 32) |
                    (unsigned long long)(0xFFFFFFFFu - (unsigned)s1);
    }
}

// ---------------- kernel 2: per-expert exact radix select ----------------
__global__ void k2_select() {
    int e = blockIdx.x;
    int tid = threadIdx.x;
    __shared__ int hist[256];
    __shared__ unsigned long long sh_prefix;
    __shared__ int sh_rem;
    __shared__ int sh_n;

    int cnt = 0;
    for (int s = tid; s < TK; s += 256) if (g_eid[s] == e) cnt++;
    if (tid == 0) sh_n = 0;
    __syncthreads();
    atomicAdd(&sh_n, cnt);
    __syncthreads();
    int n = sh_n;

    if (n <= CAP) {
        if (tid == 0) g_thresh[e] = 0ULL;
        return;
    }

    if (tid == 0) { sh_prefix = 0ULL; sh_rem = CAP; }
    __syncthreads();

    for (int p = 7; p >= 0; --p) {
        if (tid < 256) hist[tid] = 0;
        __syncthreads();
        unsigned long long prefix = sh_prefix;
        int shift_lo = p * 8;
        for (int s = tid; s < TK; s += 256) {
            if (g_eid[s] != e) continue;
            unsigned long long key = g_key[s];
            bool match = (p == 7) || (((key ^ prefix) >> ((p + 1) * 8)) == 0ULL);
            if (match)
                atomicAdd(&hist[(int)((key >> shift_lo) & 255ULL)], 1);
        }
        __syncthreads();
        if (tid == 0) {
            int rem = sh_rem;
            int cum = 0, d = 255;
            for (; d > 0; --d) { cum += hist[d]; if (cum >= rem) break; }
            if (cum < rem) cum += hist[0];
            sh_prefix |= ((unsigned long long)d) << shift_lo;
            sh_rem = rem - (cum - hist[d]);
        }
        __syncthreads();
    }
    if (tid == 0) g_thresh[e] = sh_prefix;
}

// ---------------- kernel 3: compaction ----------------
__global__ void k3_compact() {
    int s = blockIdx.x * blockDim.x + threadIdx.x;
    if (s >= TK) return;
    int e = g_eid[s];
    if (g_key[s] >= g_thresh[e]) {
        int pos = atomicAdd(&g_cnt[e], 1);
        if (pos < CAP) {
            g_tok[e][pos] = s >> 1;
            g_w[e][pos] = g_val[s];
        }
    }
}

// ---------------- kernel 4: gate_up GEMM (fp16 asym x2) + SiLU*up -----------
__global__ __launch_bounds__(256) void k4_gemm1() {
    const int e = blockIdx.z, m0 = blockIdx.x * 128, n0 = blockIdx.y * 64;
    __shared__ ushort_t Ah[2][128][24], Al[2][128][24];
    __shared__ ushort_t Bgu[2][128][24];   // rows 0-63 gate, 64-127 up

    const int tid = threadIdx.x, warp = tid >> 5, lane = tid & 31;
    const int wm = warp >> 1, wn = warp & 1;
    const int gID = lane >> 2, t4 = lane & 3;

    const int rowA = tid >> 1, chA = (tid & 1) * 8;
    const int tokA = g_tok[e][m0 + rowA];
    const ushort_t* gxh = g_xh + (size_t)tokA * CDIM + chA;
    const ushort_t* gxl = g_xl + (size_t)tokA * CDIM + chA;

    // B loader: rowA<64 -> gate, else up
    const ushort_t* gB = (rowA < 64)
        ? g_wg + ((size_t)e * NP + n0 + rowA) * CDIM + chA
        : g_wu + ((size_t)e * NP + n0 + (rowA - 64)) * CDIM + chA;

    float acc[2][2][4][4] = {};   // [gu][mt][nt][q]

    auto load = [&](int it, int buf) {
        cp16(saddr(&Ah[buf][rowA][chA]), gxh + it * 16);
        cp16(saddr(&Al[buf][rowA][chA]), gxl + it * 16);
        cp16(saddr(&Bgu[buf][rowA][chA]), gB + it * 16);
        cpcommit();
    };

    load(0, 0);

#pragma unroll 1
    for (int it = 0; it < CDIM / 16; ++it) {
        if (it + 1 < CDIM / 16) { load(it + 1, (it + 1) & 1); cpwait<1>(); }
        else cpwait<0>();
        __syncthreads();

        const int buf = it & 1;
        uint32_t a_h[2][4], a_l[2][4];
#pragma unroll
        for (int mt = 0; mt < 2; ++mt) {
            int r = wm * 32 + mt * 16 + gID;
            a_h[mt][0] = *(uint32_t*)&Ah[buf][r][2 * t4];
            a_h[mt][1] = *(uint32_t*)&Ah[buf][r + 8][2 * t4];
            a_h[mt][2] = *(uint32_t*)&Ah[buf][r][2 * t4 + 8];
            a_h[mt][3] = *(uint32_t*)&Ah[buf][r + 8][2 * t4 + 8];
            a_l[mt][0] = *(uint32_t*)&Al[buf][r][2 * t4];
            a_l[mt][1] = *(uint32_t*)&Al[buf][r + 8][2 * t4];
            a_l[mt][2] = *(uint32_t*)&Al[buf][r][2 * t4 + 8];
            a_l[mt][3] = *(uint32_t*)&Al[buf][r + 8][2 * t4 + 8];
        }
#pragma unroll
        for (int g = 0; g < 2; ++g) {
            uint32_t b[4][2];
#pragma unroll
            for (int nt = 0; nt < 4; ++nt) {
                int c = g * 64 + wn * 32 + nt * 8 + gID;
                b[nt][0] = *(uint32_t*)&Bgu[buf][c][2 * t4];
                b[nt][1] = *(uint32_t*)&Bgu[buf][c][2 * t4 + 8];
            }
#pragma unroll
            for (int mt = 0; mt < 2; ++mt)
#pragma unroll
                for (int nt = 0; nt < 4; ++nt) {
                    mma16(acc[g][mt][nt], a_h[mt], b[nt]);
                    mma16(acc[g][mt][nt], a_l[mt], b[nt]);
                }
        }
        __syncthreads();
    }

    // epilogue: silu(g)*u, split fp16 hi/lo, packed pair writes
    ushort_t* ph = g_acth + (size_t)e * CAP * AST;
    ushort_t* pl = g_actl + (size_t)e * CAP * AST;
#pragma unroll
    for (int mt = 0; mt < 2; ++mt)
#pragma unroll
        for (int nt = 0; nt < 4; ++nt) {
            int rbase = m0 + wm * 32 + mt * 16 + gID;
            int col = n0 + wn * 32 + nt * 8 + 2 * t4;
            if (col >= INTER) continue;
#pragma unroll
            for (int rq = 0; rq < 2; ++rq) {
                int row = rbase + rq * 8;
                float g0 = acc[0][mt][nt][rq * 2],     u0 = acc[1][mt][nt][rq * 2];
                float g1 = acc[0][mt][nt][rq * 2 + 1], u1 = acc[1][mt][nt][rq * 2 + 1];
                float a0 = __fdividef(g0, 1.0f + __expf(-g0)) * u0;
                float a1 = __fdividef(g1, 1.0f + __expf(-g1)) * u1;
                ushort_t h0 = f2h(a0), h1 = f2h(a1);
                ushort_t l0 = f2h(a0 - h2f(h0)), l1 = f2h(a1 - h2f(h1));
                *(uint32_t*)(ph + (size_t)row * AST + col) = (uint32_t)h0 | ((uint32_t)h1 << 16);
                *(uint32_t*)(pl + (size_t)row * AST + col) = (uint32_t)l0 | ((uint32_t)l1 << 16);
            }
        }
}

// ---------------- kernel 5: down GEMM (fp16 asym x2) + scatter --------------
__global__ __launch_bounds__(256) void k5_gemm2(float* __restrict__ out) {
    const int e = blockIdx.z, m0 = blockIdx.x * 128, n0 = blockIdx.y * 64;
    __shared__ ushort_t Ah[2][128][24], Al[2][128][24];
    __shared__ ushort_t Bs[2][64][24];

    const int tid = threadIdx.x, warp = tid >> 5, lane = tid & 31;
    const int wm = warp >> 1, wn = warp & 1;
    const int gID = lane >> 2, t4 = lane & 3;

    const int rowA = tid >> 1, chA = (tid & 1) * 8;
    const ushort_t* gah = g_acth + ((size_t)e * CAP + m0 + rowA) * AST + chA;
    const ushort_t* gal = g_actl + ((size_t)e * CAP + m0 + rowA) * AST + chA;

    const int r7 = tid & 127;
    const int rowB = r7 >> 1, chB = (r7 & 1) * 8;
    const ushort_t* gB = g_wd + ((size_t)e * CDIM + n0 + rowB) * KP + chB;
    const bool doB = (tid < 128);

    float acc[2][4][4] = {};

    auto load = [&](int it, int buf) {
        cp16(saddr(&Ah[buf][rowA][chA]), gah + it * 16);
        cp16(saddr(&Al[buf][rowA][chA]), gal + it * 16);
        if (doB) cp16(saddr(&Bs[buf][rowB][chB]), gB + it * 16);
        cpcommit();
    };

    const int NIT = KP / 16;   // 172
    load(0, 0);

#pragma unroll 1
    for (int it = 0; it < NIT; ++it) {
        if (it + 1 < NIT) { load(it + 1, (it + 1) & 1); cpwait<1>(); }
        else cpwait<0>();
        __syncthreads();

        const int buf = it & 1;
        uint32_t a_h[2][4], a_l[2][4];
#pragma unroll
        for (int mt = 0; mt < 2; ++mt) {
            int r = wm * 32 + mt * 16 + gID;
            a_h[mt][0] = *(uint32_t*)&Ah[buf][r][2 * t4];
            a_h[mt][1] = *(uint32_t*)&Ah[buf][r + 8][2 * t4];
            a_h[mt][2] = *(uint32_t*)&Ah[buf][r][2 * t4 + 8];
            a_h[mt][3] = *(uint32_t*)&Ah[buf][r + 8][2 * t4 + 8];
            a_l[mt][0] = *(uint32_t*)&Al[buf][r][2 * t4];
            a_l[mt][1] = *(uint32_t*)&Al[buf][r + 8][2 * t4];
            a_l[mt][2] = *(uint32_t*)&Al[buf][r][2 * t4 + 8];
            a_l[mt][3] = *(uint32_t*)&Al[buf][r + 8][2 * t4 + 8];
        }
        uint32_t b[4][2];
#pragma unroll
        for (int nt = 0; nt < 4; ++nt) {
            int c = wn * 32 + nt * 8 + gID;
            b[nt][0] = *(uint32_t*)&Bs[buf][c][2 * t4];
            b[nt][1] = *(uint32_t*)&Bs[buf][c][2 * t4 + 8];
        }
#pragma unroll
        for (int mt = 0; mt < 2; ++mt)
#pragma unroll
            for (int nt = 0; nt < 4; ++nt) {
                mma16(acc[mt][nt], a_h[mt], b[nt]);
                mma16(acc[mt][nt], a_l[mt], b[nt]);
            }
        __syncthreads();
    }

    // epilogue: scale by routing weight, atomic scatter
#pragma unroll
    for (int mt = 0; mt < 2; ++mt)
#pragma unroll
        for (int rq = 0; rq < 2; ++rq) {
            int row = m0 + wm * 32 + mt * 16 + gID + rq * 8;
            float w = g_w[e][row];
            if (w == 0.0f) continue;
            int tok = g_tok[e][row];
            float* orow = out + (size_t)tok * CDIM;
#pragma unroll
            for (int nt = 0; nt < 4; ++nt) {
                int col = n0 + wn * 32 + nt * 8 + 2 * t4;
                atomicAdd(&orow[col],     acc[mt][nt][rq * 2 + 0] * w);
                atomicAdd(&orow[col + 1], acc[mt][nt][rq * 2 + 1] * w);
            }
        }
}

// ---------------- launch ----------------
extern "C" void kernel_launch(void* const* d_in, const int* in_sizes, int n_in,
                              void* d_out, int out_size) {
    const float* x    = (const float*)d_in[0];
    const float* cond = (const float*)d_in[1];
    const float* snr  = (const float*)d_in[2];
    const float* gw   = (const float*)d_in[3];
    const float* wgu  = (const float*)d_in[4];
    const float* wd   = (const float*)d_in[5];
    float* out = (float*)d_out;

    k0_init<<<1024, 256>>>(out, out_size);
    ksplit_x<<<2048, 256>>>(x);
    {
        dim3 b(32, 8);
        dim3 g1((N2 + 31) / 32, CDIM / 32, NE);
        ksplit_gu_t<<<g1, b>>>(wgu);
        dim3 g2(CDIM / 32, (INTER + 31) / 32, NE);
        ksplit_dw_t<<<g2, b>>>(wd);
    }
    k1_gate<<<(T_TOK * 32 + 255) / 256, 256>>>(x, cond, snr, gw);
    k2_select<<<NE, 256>>>();
    k3_compact<<<TK / 256, 256>>>();

    dim3 gg1(CAP / 128, NP / 64, NE);    // 20 x 43 x 8
    k4_gemm1<<<gg1, 256>>>();

    dim3 gg2(CAP / 128, CDIM / 64, NE);  // 20 x 16 x 8
    k5_gemm2<<<gg2, 256>>>(out);
}

// round 7
// speedup vs baseline: 2.8687x; 1.0844x over previous
#include <cuda_runtime.h>
#include <cuda_fp16.h>
#include <cstdint>
#include <math.h>

// Problem constants
#define T_TOK 16384
#define TK    32768
#define NE    8
#define CDIM  1024
#define INTER 2730
#define N2    5460
#define CAP   2560
#define AST   2752   // activation k-stride (zero tail)
#define NP    2752   // padded n-rows for gate/up transposed weights
#define KP    2752   // padded k-stride for transposed down weights

typedef unsigned short ushort_t;

// ---------------- scratch (device globals; zero-initialized) ----------------
__device__ unsigned long long g_key[TK];
__device__ int   g_eid[TK];
__device__ float g_val[TK];
__device__ unsigned long long g_thresh[NE];
__device__ int   g_cnt[NE];
__device__ int   g_tok[NE][CAP];
__device__ float g_w[NE][CAP];

__device__ ushort_t g_xh[(size_t)T_TOK * CDIM];
__device__ ushort_t g_xl[(size_t)T_TOK * CDIM];
__device__ ushort_t g_wg[(size_t)NE * NP * CDIM];    // gate, [e][n][k]
__device__ ushort_t g_wu[(size_t)NE * NP * CDIM];    // up,   [e][n][k]
__device__ ushort_t g_wd[(size_t)NE * CDIM * KP];    // down, [e][n][k]
__device__ ushort_t g_acth[(size_t)NE * CAP * AST];
__device__ ushort_t g_actl[(size_t)NE * CAP * AST];

// ---------------- helpers ----------------
__device__ __forceinline__ ushort_t f2h(float f) {
    __half h = __float2half_rn(f);
    return *(ushort_t*)&h;
}
__device__ __forceinline__ float h2f(ushort_t u) {
    __half h = *(__half*)&u;
    return __half2float(h);
}
__device__ __forceinline__ uint32_t saddr(const void* p) {
    return (uint32_t)__cvta_generic_to_shared(p);
}
__device__ __forceinline__ void cp16(uint32_t d, const void* s) {
    asm volatile("cp.async.cg.shared.global [%0], [%1], 16;\n" :: "r"(d), "l"(s));
}
__device__ __forceinline__ void cpcommit() { asm volatile("cp.async.commit_group;\n"); }
template<int N> __device__ __forceinline__ void cpwait() {
    asm volatile("cp.async.wait_group %0;\n" :: "n"(N));
}
__device__ __forceinline__ void ldsm4(uint32_t* r, uint32_t a) {
    asm volatile("ldmatrix.sync.aligned.m8n8.x4.shared.b16 {%0,%1,%2,%3}, [%4];"
                 : "=r"(r[0]), "=r"(r[1]), "=r"(r[2]), "=r"(r[3]) : "r"(a));
}
__device__ __forceinline__ void mma16(float* c, const uint32_t* a, const uint32_t* b) {
    asm volatile(
        "mma.sync.aligned.m16n8k16.row.col.f32.f16.f16.f32 "
        "{%0,%1,%2,%3},{%4,%5,%6,%7},{%8,%9},{%0,%1,%2,%3};"
        : "+f"(c[0]), "+f"(c[1]), "+f"(c[2]), "+f"(c[3])
        : "r"(a[0]), "r"(a[1]), "r"(a[2]), "r"(a[3]), "r"(b[0]), "r"(b[1]));
}

// ---------------- kernel 0: init ----------------
__global__ void k0_init(float* out, int out_size) {
    int i = blockIdx.x * blockDim.x + threadIdx.x;
    int stride = gridDim.x * blockDim.x;
    for (int j = i; j < out_size; j += stride) out[j] = 0.0f;
    if (i < NE) g_cnt[i] = 0;
    for (int j = i; j < NE * CAP; j += stride) {
        ((int*)g_tok)[j] = 0;
        ((float*)g_w)[j] = 0.0f;
    }
}

// ---------------- split x -> fp16 hi/lo ----------------
__global__ void ksplit_x(const float* __restrict__ s) {
    const int n = T_TOK * CDIM;
    int i = blockIdx.x * blockDim.x + threadIdx.x;
    int stride = gridDim.x * blockDim.x;
    for (int j = i * 4; j < n; j += stride * 4) {
        float4 v = *(const float4*)(s + j);
        float* pv = (float*)&v;
        uint32_t h[2], l[2];
#pragma unroll
        for (int p = 0; p < 2; ++p) {
            ushort_t h0 = f2h(pv[2*p]);
            ushort_t h1 = f2h(pv[2*p+1]);
            ushort_t l0 = f2h(pv[2*p]   - h2f(h0));
            ushort_t l1 = f2h(pv[2*p+1] - h2f(h1));
            h[p] = (uint32_t)h0 | ((uint32_t)h1 << 16);
            l[p] = (uint32_t)l0 | ((uint32_t)l1 << 16);
        }
        *(uint32_t*)(g_xh + j)     = h[0];
        *(uint32_t*)(g_xh + j + 2) = h[1];
        *(uint32_t*)(g_xl + j)     = l[0];
        *(uint32_t*)(g_xl + j + 2) = l[1];
    }
}

// ---------------- transpose gate_up_w [e][k][5460] -> fp16 [e][n][k] --------
__global__ void ksplit_gu_t(const float* __restrict__ s) {
    __shared__ float tile[32][33];
    const int e = blockIdx.z;
    const int n0 = blockIdx.x * 32, k0 = blockIdx.y * 32;
    const int tx = threadIdx.x, ty = threadIdx.y;
    for (int i = ty; i < 32; i += 8) {
        int n = n0 + tx, k = k0 + i;
        tile[i][tx] = (n < N2) ? s[((size_t)e * CDIM + k) * N2 + n] : 0.0f;
    }
    __syncthreads();
    for (int i = ty; i < 32; i += 8) {
        int n = n0 + i, k = k0 + tx;
        if (n >= N2) continue;
        ushort_t h = f2h(tile[tx][i]);
        if (n < INTER) {
            g_wg[((size_t)e * NP + n) * CDIM + k] = h;
        } else {
            g_wu[((size_t)e * NP + (n - INTER)) * CDIM + k] = h;
        }
    }
}

// ---------------- transpose down_w [e][k=INTER][n=CDIM] -> fp16 [e][n][k] ---
__global__ void ksplit_dw_t(const float* __restrict__ s) {
    __shared__ float tile[32][33];
    const int e = blockIdx.z;
    const int n0 = blockIdx.x * 32, k0 = blockIdx.y * 32;
    const int tx = threadIdx.x, ty = threadIdx.y;
    for (int i = ty; i < 32; i += 8) {
        int k = k0 + i;
        tile[i][tx] = (k < INTER) ? s[((size_t)e * INTER + k) * CDIM + n0 + tx] : 0.0f;
    }
    __syncthreads();
    for (int i = ty; i < 32; i += 8) {
        int n = n0 + i, k = k0 + tx;
        if (k >= INTER) continue;
        g_wd[((size_t)e * CDIM + n) * KP + k] = f2h(tile[tx][i]);
    }
}

// ---------------- kernel 1: gating (one warp per token) ----------------
__global__ void k1_gate(const float* __restrict__ x, const float* __restrict__ cond,
                        const float* __restrict__ snr, const float* __restrict__ gw) {
    int warp = (blockIdx.x * blockDim.x + threadIdx.x) >> 5;
    int lane = threadIdx.x & 31;
    if (warp >= T_TOK) return;
    int t = warp;
    int b = t >> 12;

    float acc[NE];
#pragma unroll
    for (int e = 0; e < NE; ++e) acc[e] = 0.0f;

    const float* xr = x + (size_t)t * CDIM;
    const float* cr = cond + (size_t)b * CDIM;
    for (int d = lane; d < 2 * CDIM; d += 32) {
        float v = (d < CDIM) ? xr[d] : cr[d - CDIM];
        const float* wrow = gw + (size_t)d * NE;
#pragma unroll
        for (int e = 0; e < NE; ++e) acc[e] += v * wrow[e];
    }
#pragma unroll
    for (int e = 0; e < NE; ++e) {
#pragma unroll
        for (int o = 16; o > 0; o >>= 1)
            acc[e] += __shfl_xor_sync(0xFFFFFFFFu, acc[e], o);
    }

    if (lane == 0) {
        bool hn = snr[b] < 0.5f;
        float lg[NE];
#pragma unroll
        for (int e = 0; e < NE; ++e)
            lg[e] = (hn && e >= 2) ? -INFINITY : acc[e];

        float mx = lg[0];
#pragma unroll
        for (int e = 1; e < NE; ++e) mx = fmaxf(mx, lg[e]);
        float p[NE], s = 0.0f;
#pragma unroll
        for (int e = 0; e < NE; ++e) { p[e] = expf(lg[e] - mx); s += p[e]; }
        float inv = 1.0f / s;
#pragma unroll
        for (int e = 0; e < NE; ++e) p[e] *= inv;

        int i0 = 0; float p0 = p[0];
#pragma unroll
        for (int e = 1; e < NE; ++e) if (p[e] > p0) { p0 = p[e]; i0 = e; }
        int i1 = -1; float p1 = -1.0f;
#pragma unroll
        for (int e = 0; e < NE; ++e) if (e != i0 && p[e] > p1) { p1 = p[e]; i1 = e; }

        float denom = fmaxf(p0 + p1, 1e-12f);
        float w0 = p0 / denom, w1 = p1 / denom;

        int s0 = t * 2, s1 = t * 2 + 1;
        g_eid[s0] = i0; g_val[s0] = w0;
        g_key[s0] = ((unsigned long long)__float_as_uint(w0) << 32) |
                    (unsigned long long)(0xFFFFFFFFu - (unsigned)s0);
        g_eid[s1] = i1; g_val[s1] = w1;
        g_key[s1] = ((unsigned long long)__float_as_uint(w1) << 32) |
                    (unsigned long long)(0xFFFFFFFFu - (unsigned)s1);
    }
}

// ---------------- kernel 2: per-expert exact radix select ----------------
__global__ void k2_select() {
    int e = blockIdx.x;
    int tid = threadIdx.x;
    __shared__ int hist[256];
    __shared__ unsigned long long sh_prefix;
    __shared__ int sh_rem;
    __shared__ int sh_n;

    int cnt = 0;
    for (int s = tid; s < TK; s += 256) if (g_eid[s] == e) cnt++;
    if (tid == 0) sh_n = 0;
    __syncthreads();
    atomicAdd(&sh_n, cnt);
    __syncthreads();
    int n = sh_n;

    if (n <= CAP) {
        if (tid == 0) g_thresh[e] = 0ULL;
        return;
    }

    if (tid == 0) { sh_prefix = 0ULL; sh_rem = CAP; }
    __syncthreads();

    for (int p = 7; p >= 0; --p) {
        if (tid < 256) hist[tid] = 0;
        __syncthreads();
        unsigned long long prefix = sh_prefix;
        int shift_lo = p * 8;
        for (int s = tid; s < TK; s += 256) {
            if (g_eid[s] != e) continue;
            unsigned long long key = g_key[s];
            bool match = (p == 7) || (((key ^ prefix) >> ((p + 1) * 8)) == 0ULL);
            if (match)
                atomicAdd(&hist[(int)((key >> shift_lo) & 255ULL)], 1);
        }
        __syncthreads();
        if (tid == 0) {
            int rem = sh_rem;
            int cum = 0, d = 255;
            for (; d > 0; --d) { cum += hist[d]; if (cum >= rem) break; }
            if (cum < rem) cum += hist[0];
            sh_prefix |= ((unsigned long long)d) << shift_lo;
            sh_rem = rem - (cum - hist[d]);
        }
        __syncthreads();
    }
    if (tid == 0) g_thresh[e] = sh_prefix;
}

// ---------------- kernel 3: compaction ----------------
__global__ void k3_compact() {
    int s = blockIdx.x * blockDim.x + threadIdx.x;
    if (s >= TK) return;
    int e = g_eid[s];
    if (g_key[s] >= g_thresh[e]) {
        int pos = atomicAdd(&g_cnt[e], 1);
        if (pos < CAP) {
            g_tok[e][pos] = s >> 1;
            g_w[e][pos] = g_val[s];
        }
    }
}

// ======================= GEMM kernels: BK=32, 3-stage, ldmatrix =============
// smem row stride: 40 halves (80B) — conflict-free for ldmatrix & cp.async
#define RS 40

// ---------------- kernel 4: gate_up GEMM (fp16 asym x2) + SiLU*up -----------
// stage layout (bytes): Ah @0 (10240), Al @10240, B @20480 (128 rows: gate 0-63, up 64-127)
#define K4_STG 30720
__global__ __launch_bounds__(256) void k4_gemm1() {
    extern __shared__ char sm[];
    const uint32_t base = saddr(sm);
    const int e = blockIdx.z, m0 = blockIdx.x * 128, n0 = blockIdx.y * 64;
    const int tid = threadIdx.x, warp = tid >> 5, lane = tid & 31;
    const int wm = warp >> 1, wn = warp & 1;
    const int gID = lane >> 2, t4 = lane & 3;

    // loaders
    const int rowA = tid >> 1;
    const int cb = (tid & 1) * 32;           // byte offset within row
    const int chH = cb >> 1;                 // halves
    const int tokA = g_tok[e][m0 + rowA];
    const ushort_t* gxh = g_xh + (size_t)tokA * CDIM + chH;
    const ushort_t* gxl = g_xl + (size_t)tokA * CDIM + chH;
    const ushort_t* gB = (rowA < 64)
        ? g_wg + ((size_t)e * NP + n0 + rowA) * CDIM + chH
        : g_wu + ((size_t)e * NP + n0 + (rowA - 64)) * CDIM + chH;
    const uint32_t dRow = (uint32_t)(rowA * (RS * 2) + cb);

    auto load = [&](int it, int st) {
        uint32_t s = base + st * K4_STG;
        const ushort_t* ph = gxh + it * 32;
        const ushort_t* pl = gxl + it * 32;
        const ushort_t* pb = gB + it * 32;
        cp16(s + dRow,              ph);
        cp16(s + dRow + 16,         ph + 8);
        cp16(s + 10240 + dRow,      pl);
        cp16(s + 10240 + dRow + 16, pl + 8);
        cp16(s + 20480 + dRow,      pb);
        cp16(s + 20480 + dRow + 16, pb + 8);
        cpcommit();
    };

    // fragment base offsets (bytes within stage)
    const uint32_t aoff = (uint32_t)((wm * 32 + (lane & 15)) * (RS * 2) + ((lane >> 4) * 8) * 2);
    const uint32_t boff = (uint32_t)((((lane & 7) + ((lane >> 4) & 1) * 8)) * (RS * 2) +
                                     (((lane >> 3) & 1) * 8) * 2);

    float acc[2][2][4][4] = {};   // [gu][mt][nt][q]

    const int NIT = CDIM / 32;   // 32
    load(0, 0);
    load(1, 1);

#pragma unroll 1
    for (int it = 0; it < NIT; ++it) {
        if (it + 1 < NIT) cpwait<1>(); else cpwait<0>();
        __syncthreads();
        if (it + 2 < NIT) load(it + 2, (it + 2) % 3);

        const uint32_t s = base + (it % 3) * K4_STG;
#pragma unroll
        for (int ks = 0; ks < 2; ++ks) {
            uint32_t ah[2][4], al[2][4], bb[2][2][4];
#pragma unroll
            for (int mt = 0; mt < 2; ++mt) {
                ldsm4(ah[mt], s + aoff + mt * 16 * (RS * 2) + ks * 32);
                ldsm4(al[mt], s + 10240 + aoff + mt * 16 * (RS * 2) + ks * 32);
            }
#pragma unroll
            for (int g = 0; g < 2; ++g)
#pragma unroll
                for (int np = 0; np < 2; ++np)
                    ldsm4(bb[g][np], s + 20480 + boff +
                          (g * 64 + wn * 32 + np * 16) * (RS * 2) + ks * 32);
#pragma unroll
            for (int g = 0; g < 2; ++g)
#pragma unroll
                for (int mt = 0; mt < 2; ++mt)
#pragma unroll
                    for (int nt = 0; nt < 4; ++nt) {
                        const uint32_t* bp = &bb[g][nt >> 1][(nt & 1) * 2];
                        mma16(acc[g][mt][nt], ah[mt], bp);
                        mma16(acc[g][mt][nt], al[mt], bp);
                    }
        }
        __syncthreads();
    }

    // epilogue: silu(g)*u, split fp16 hi/lo
    ushort_t* ph = g_acth + (size_t)e * CAP * AST;
    ushort_t* pl = g_actl + (size_t)e * CAP * AST;
#pragma unroll
    for (int mt = 0; mt < 2; ++mt)
#pragma unroll
        for (int nt = 0; nt < 4; ++nt) {
            int rbase = m0 + wm * 32 + mt * 16 + gID;
            int col = n0 + wn * 32 + nt * 8 + 2 * t4;
            if (col >= INTER) continue;
#pragma unroll
            for (int rq = 0; rq < 2; ++rq) {
                int row = rbase + rq * 8;
                float g0 = acc[0][mt][nt][rq * 2],     u0 = acc[1][mt][nt][rq * 2];
                float g1 = acc[0][mt][nt][rq * 2 + 1], u1 = acc[1][mt][nt][rq * 2 + 1];
                float a0 = __fdividef(g0, 1.0f + __expf(-g0)) * u0;
                float a1 = __fdividef(g1, 1.0f + __expf(-g1)) * u1;
                ushort_t h0 = f2h(a0), h1 = f2h(a1);
                ushort_t l0 = f2h(a0 - h2f(h0)), l1 = f2h(a1 - h2f(h1));
                *(uint32_t*)(ph + (size_t)row * AST + col) = (uint32_t)h0 | ((uint32_t)h1 << 16);
                *(uint32_t*)(pl + (size_t)row * AST + col) = (uint32_t)l0 | ((uint32_t)l1 << 16);
            }
        }
}

// ---------------- kernel 5: down GEMM (fp16 asym x2) + scatter --------------
// stage layout: Ah @0 (10240), Al @10240, B @20480 (64 rows, 5120B)
#define K5_STG 25600
__global__ __launch_bounds__(256) void k5_gemm2(float* __restrict__ out) {
    extern __shared__ char sm[];
    const uint32_t base = saddr(sm);
    const int e = blockIdx.z, m0 = blockIdx.x * 128, n0 = blockIdx.y * 64;
    const int tid = threadIdx.x, warp = tid >> 5, lane = tid & 31;
    const int wm = warp >> 1, wn = warp & 1;
    const int gID = lane >> 2, t4 = lane & 3;

    const int rowA = tid >> 1;
    const int cb = (tid & 1) * 32;
    const int chH = cb >> 1;
    const ushort_t* gah = g_acth + ((size_t)e * CAP + m0 + rowA) * AST + chH;
    const ushort_t* gal = g_actl + ((size_t)e * CAP + m0 + rowA) * AST + chH;
    const uint32_t dRowA = (uint32_t)(rowA * (RS * 2) + cb);

    const int rowB = tid >> 2;
    const int cbB = (tid & 3) * 16;
    const ushort_t* gB = g_wd + ((size_t)e * CDIM + n0 + rowB) * KP + (cbB >> 1);
    const uint32_t dRowB = (uint32_t)(rowB * (RS * 2) + cbB);

    auto load = [&](int it, int st) {
        uint32_t s = base + st * K5_STG;
        const ushort_t* ph = gah + it * 32;
        const ushort_t* pl = gal + it * 32;
        cp16(s + dRowA,              ph);
        cp16(s + dRowA + 16,         ph + 8);
        cp16(s + 10240 + dRowA,      pl);
        cp16(s + 10240 + dRowA + 16, pl + 8);
        cp16(s + 20480 + dRowB,      gB + it * 32);
        cpcommit();
    };

    const uint32_t aoff = (uint32_t)((wm * 32 + (lane & 15)) * (RS * 2) + ((lane >> 4) * 8) * 2);
    const uint32_t boff = (uint32_t)((((lane & 7) + ((lane >> 4) & 1) * 8)) * (RS * 2) +
                                     (((lane >> 3) & 1) * 8) * 2);

    float acc[2][4][4] = {};

    const int NIT = KP / 32;   // 86
    load(0, 0);
    load(1, 1);

#pragma unroll 1
    for (int it = 0; it < NIT; ++it) {
        if (it + 1 < NIT) cpwait<1>(); else cpwait<0>();
        __syncthreads();
        if (it + 2 < NIT) load(it + 2, (it + 2) % 3);

        const uint32_t s = base + (it % 3) * K5_STG;
#pragma unroll
        for (int ks = 0; ks < 2; ++ks) {
            uint32_t ah[2][4], al[2][4], bb[2][4];
#pragma unroll
            for (int mt = 0; mt < 2; ++mt) {
                ldsm4(ah[mt], s + aoff + mt * 16 * (RS * 2) + ks * 32);
                ldsm4(al[mt], s + 10240 + aoff + mt * 16 * (RS * 2) + ks * 32);
            }
#pragma unroll
            for (int np = 0; np < 2; ++np)
                ldsm4(bb[np], s + 20480 + boff + (wn * 32 + np * 16) * (RS * 2) + ks * 32);
#pragma unroll
            for (int mt = 0; mt < 2; ++mt)
#pragma unroll
                for (int nt = 0; nt < 4; ++nt) {
                    const uint32_t* bp = &bb[nt >> 1][(nt & 1) * 2];
                    mma16(acc[mt][nt], ah[mt], bp);
                    mma16(acc[mt][nt], al[mt], bp);
                }
        }
        __syncthreads();
    }

    // epilogue: scale by routing weight, atomic scatter
#pragma unroll
    for (int mt = 0; mt < 2; ++mt)
#pragma unroll
        for (int rq = 0; rq < 2; ++rq) {
            int row = m0 + wm * 32 + mt * 16 + gID + rq * 8;
            float w = g_w[e][row];
            if (w == 0.0f) continue;
            int tok = g_tok[e][row];
            float* orow = out + (size_t)tok * CDIM;
#pragma unroll
            for (int nt = 0; nt < 4; ++nt) {
                int col = n0 + wn * 32 + nt * 8 + 2 * t4;
                atomicAdd(&orow[col],     acc[mt][nt][rq * 2 + 0] * w);
                atomicAdd(&orow[col + 1], acc[mt][nt][rq * 2 + 1] * w);
            }
        }
}

// ---------------- launch ----------------
extern "C" void kernel_launch(void* const* d_in, const int* in_sizes, int n_in,
                              void* d_out, int out_size) {
    const float* x    = (const float*)d_in[0];
    const float* cond = (const float*)d_in[1];
    const float* snr  = (const float*)d_in[2];
    const float* gw   = (const float*)d_in[3];
    const float* wgu  = (const float*)d_in[4];
    const float* wd   = (const float*)d_in[5];
    float* out = (float*)d_out;

    cudaFuncSetAttribute(k4_gemm1, cudaFuncAttributeMaxDynamicSharedMemorySize, 3 * K4_STG);
    cudaFuncSetAttribute(k5_gemm2, cudaFuncAttributeMaxDynamicSharedMemorySize, 3 * K5_STG);

    k0_init<<<1024, 256>>>(out, out_size);
    ksplit_x<<<2048, 256>>>(x);
    {
        dim3 b(32, 8);
        dim3 g1((N2 + 31) / 32, CDIM / 32, NE);
        ksplit_gu_t<<<g1, b>>>(wgu);
        dim3 g2(CDIM / 32, (INTER + 31) / 32, NE);
        ksplit_dw_t<<<g2, b>>>(wd);
    }
    k1_gate<<<(T_TOK * 32 + 255) / 256, 256>>>(x, cond, snr, gw);
    k2_select<<<NE, 256>>>();
    k3_compact<<<TK / 256, 256>>>();

    dim3 gg1(CAP / 128, NP / 64, NE);    // 20 x 43 x 8
    k4_gemm1<<<gg1, 256, 3 * K4_STG>>>();

    dim3 gg2(CAP / 128, CDIM / 64, NE);  // 20 x 16 x 8
    k5_gemm2<<<gg2, 256, 3 * K5_STG>>>(out);
}

// round 8
// speedup vs baseline: 3.5462x; 1.2362x over previous
#include <cuda_runtime.h>
#include <cuda_fp16.h>
#include <cstdint>
#include <math.h>

// Problem constants
#define T_TOK 16384
#define TK    32768
#define NE    8
#define CDIM  1024
#define INTER 2730
#define N2    5460
#define CAP   2560
#define AST   2752   // activation k-stride (zero tail)
#define NP    2752   // padded n-rows for gate/up transposed weights
#define KP    2752   // padded k-stride for transposed down weights

typedef unsigned short ushort_t;

// ---------------- scratch (device globals; zero-initialized) ----------------
__device__ unsigned long long g_key[TK];
__device__ int   g_eid[TK];
__device__ float g_val[TK];
__device__ unsigned long long g_thresh[NE];
__device__ int   g_cnt[NE];
__device__ int   g_tok[NE][CAP];
__device__ float g_w[NE][CAP];

__device__ ushort_t g_x16[(size_t)T_TOK * CDIM];
__device__ ushort_t g_wg[(size_t)NE * NP * CDIM];    // gate, [e][n][k]
__device__ ushort_t g_wu[(size_t)NE * NP * CDIM];    // up,   [e][n][k]
__device__ ushort_t g_wd[(size_t)NE * CDIM * KP];    // down, [e][n][k]
__device__ ushort_t g_act[(size_t)NE * CAP * AST];

// ---------------- helpers ----------------
__device__ __forceinline__ ushort_t f2h(float f) {
    __half h = __float2half_rn(f);
    return *(ushort_t*)&h;
}
__device__ __forceinline__ uint32_t saddr(const void* p) {
    return (uint32_t)__cvta_generic_to_shared(p);
}
__device__ __forceinline__ void cp16(uint32_t d, const void* s) {
    asm volatile("cp.async.cg.shared.global [%0], [%1], 16;\n" :: "r"(d), "l"(s));
}
__device__ __forceinline__ void cpcommit() { asm volatile("cp.async.commit_group;\n"); }
template<int N> __device__ __forceinline__ void cpwait() {
    asm volatile("cp.async.wait_group %0;\n" :: "n"(N));
}
__device__ __forceinline__ void ldsm4(uint32_t* r, uint32_t a) {
    asm volatile("ldmatrix.sync.aligned.m8n8.x4.shared.b16 {%0,%1,%2,%3}, [%4];"
                 : "=r"(r[0]), "=r"(r[1]), "=r"(r[2]), "=r"(r[3]) : "r"(a));
}
__device__ __forceinline__ void mma16(float* c, const uint32_t* a, const uint32_t* b) {
    asm volatile(
        "mma.sync.aligned.m16n8k16.row.col.f32.f16.f16.f32 "
        "{%0,%1,%2,%3},{%4,%5,%6,%7},{%8,%9},{%0,%1,%2,%3};"
        : "+f"(c[0]), "+f"(c[1]), "+f"(c[2]), "+f"(c[3])
        : "r"(a[0]), "r"(a[1]), "r"(a[2]), "r"(a[3]), "r"(b[0]), "r"(b[1]));
}

// ---------------- kernel 0: init ----------------
__global__ void k0_init(float* out, int out_size) {
    int i = blockIdx.x * blockDim.x + threadIdx.x;
    int stride = gridDim.x * blockDim.x;
    for (int j = i; j < out_size; j += stride) out[j] = 0.0f;
    if (i < NE) g_cnt[i] = 0;
    for (int j = i; j < NE * CAP; j += stride) {
        ((int*)g_tok)[j] = 0;
        ((float*)g_w)[j] = 0.0f;
    }
}

// ---------------- convert x -> fp16 ----------------
__global__ void ksplit_x(const float* __restrict__ s) {
    const int n = T_TOK * CDIM;
    int i = blockIdx.x * blockDim.x + threadIdx.x;
    int stride = gridDim.x * blockDim.x;
    for (int j = i * 4; j < n; j += stride * 4) {
        float4 v = *(const float4*)(s + j);
        float* pv = (float*)&v;
        uint32_t h[2];
#pragma unroll
        for (int p = 0; p < 2; ++p) {
            ushort_t h0 = f2h(pv[2*p]);
            ushort_t h1 = f2h(pv[2*p+1]);
            h[p] = (uint32_t)h0 | ((uint32_t)h1 << 16);
        }
        *(uint32_t*)(g_x16 + j)     = h[0];
        *(uint32_t*)(g_x16 + j + 2) = h[1];
    }
}

// ---------------- transpose gate_up_w [e][k][5460] -> fp16 [e][n][k] --------
__global__ void ksplit_gu_t(const float* __restrict__ s) {
    __shared__ float tile[32][33];
    const int e = blockIdx.z;
    const int n0 = blockIdx.x * 32, k0 = blockIdx.y * 32;
    const int tx = threadIdx.x, ty = threadIdx.y;
    for (int i = ty; i < 32; i += 8) {
        int n = n0 + tx, k = k0 + i;
        tile[i][tx] = (n < N2) ? s[((size_t)e * CDIM + k) * N2 + n] : 0.0f;
    }
    __syncthreads();
    for (int i = ty; i < 32; i += 8) {
        int n = n0 + i, k = k0 + tx;
        if (n >= N2) continue;
        ushort_t h = f2h(tile[tx][i]);
        if (n < INTER) {
            g_wg[((size_t)e * NP + n) * CDIM + k] = h;
        } else {
            g_wu[((size_t)e * NP + (n - INTER)) * CDIM + k] = h;
        }
    }
}

// ---------------- transpose down_w [e][k=INTER][n=CDIM] -> fp16 [e][n][k] ---
__global__ void ksplit_dw_t(const float* __restrict__ s) {
    __shared__ float tile[32][33];
    const int e = blockIdx.z;
    const int n0 = blockIdx.x * 32, k0 = blockIdx.y * 32;
    const int tx = threadIdx.x, ty = threadIdx.y;
    for (int i = ty; i < 32; i += 8) {
        int k = k0 + i;
        tile[i][tx] = (k < INTER) ? s[((size_t)e * INTER + k) * CDIM + n0 + tx] : 0.0f;
    }
    __syncthreads();
    for (int i = ty; i < 32; i += 8) {
        int n = n0 + i, k = k0 + tx;
        if (k >= INTER) continue;
        g_wd[((size_t)e * CDIM + n) * KP + k] = f2h(tile[tx][i]);
    }
}

// ---------------- kernel 1: gating (one warp per token) ----------------
__global__ void k1_gate(const float* __restrict__ x, const float* __restrict__ cond,
                        const float* __restrict__ snr, const float* __restrict__ gw) {
    int warp = (blockIdx.x * blockDim.x + threadIdx.x) >> 5;
    int lane = threadIdx.x & 31;
    if (warp >= T_TOK) return;
    int t = warp;
    int b = t >> 12;

    float acc[NE];
#pragma unroll
    for (int e = 0; e < NE; ++e) acc[e] = 0.0f;

    const float* xr = x + (size_t)t * CDIM;
    const float* cr = cond + (size_t)b * CDIM;
    for (int d = lane; d < 2 * CDIM; d += 32) {
        float v = (d < CDIM) ? xr[d] : cr[d - CDIM];
        const float* wrow = gw + (size_t)d * NE;
#pragma unroll
        for (int e = 0; e < NE; ++e) acc[e] += v * wrow[e];
    }
#pragma unroll
    for (int e = 0; e < NE; ++e) {
#pragma unroll
        for (int o = 16; o > 0; o >>= 1)
            acc[e] += __shfl_xor_sync(0xFFFFFFFFu, acc[e], o);
    }

    if (lane == 0) {
        bool hn = snr[b] < 0.5f;
        float lg[NE];
#pragma unroll
        for (int e = 0; e < NE; ++e)
            lg[e] = (hn && e >= 2) ? -INFINITY : acc[e];

        float mx = lg[0];
#pragma unroll
        for (int e = 1; e < NE; ++e) mx = fmaxf(mx, lg[e]);
        float p[NE], s = 0.0f;
#pragma unroll
        for (int e = 0; e < NE; ++e) { p[e] = expf(lg[e] - mx); s += p[e]; }
        float inv = 1.0f / s;
#pragma unroll
        for (int e = 0; e < NE; ++e) p[e] *= inv;

        int i0 = 0; float p0 = p[0];
#pragma unroll
        for (int e = 1; e < NE; ++e) if (p[e] > p0) { p0 = p[e]; i0 = e; }
        int i1 = -1; float p1 = -1.0f;
#pragma unroll
        for (int e = 0; e < NE; ++e) if (e != i0 && p[e] > p1) { p1 = p[e]; i1 = e; }

        float denom = fmaxf(p0 + p1, 1e-12f);
        float w0 = p0 / denom, w1 = p1 / denom;

        int s0 = t * 2, s1 = t * 2 + 1;
        g_eid[s0] = i0; g_val[s0] = w0;
        g_key[s0] = ((unsigned long long)__float_as_uint(w0) << 32) |
                    (unsigned long long)(0xFFFFFFFFu - (unsigned)s0);
        g_eid[s1] = i1; g_val[s1] = w1;
        g_key[s1] = ((unsigned long long)__float_as_uint(w1) << 32) |
                    (unsigned long long)(0xFFFFFFFFu - (unsigned)s1);
    }
}

// ---------------- kernel 2: per-expert exact radix select ----------------
__global__ void k2_select() {
    int e = blockIdx.x;
    int tid = threadIdx.x;
    __shared__ int hist[256];
    __shared__ unsigned long long sh_prefix;
    __shared__ int sh_rem;
    __shared__ int sh_n;

    int cnt = 0;
    for (int s = tid; s < TK; s += 256) if (g_eid[s] == e) cnt++;
    if (tid == 0) sh_n = 0;
    __syncthreads();
    atomicAdd(&sh_n, cnt);
    __syncthreads();
    int n = sh_n;

    if (n <= CAP) {
        if (tid == 0) g_thresh[e] = 0ULL;
        return;
    }

    if (tid == 0) { sh_prefix = 0ULL; sh_rem = CAP; }
    __syncthreads();

    for (int p = 7; p >= 0; --p) {
        if (tid < 256) hist[tid] = 0;
        __syncthreads();
        unsigned long long prefix = sh_prefix;
        int shift_lo = p * 8;
        for (int s = tid; s < TK; s += 256) {
            if (g_eid[s] != e) continue;
            unsigned long long key = g_key[s];
            bool match = (p == 7) || (((key ^ prefix) >> ((p + 1) * 8)) == 0ULL);
            if (match)
                atomicAdd(&hist[(int)((key >> shift_lo) & 255ULL)], 1);
        }
        __syncthreads();
        if (tid == 0) {
            int rem = sh_rem;
            int cum = 0, d = 255;
            for (; d > 0; --d) { cum += hist[d]; if (cum >= rem) break; }
            if (cum < rem) cum += hist[0];
            sh_prefix |= ((unsigned long long)d) << shift_lo;
            sh_rem = rem - (cum - hist[d]);
        }
        __syncthreads();
    }
    if (tid == 0) g_thresh[e] = sh_prefix;
}

// ---------------- kernel 3: compaction ----------------
__global__ void k3_compact() {
    int s = blockIdx.x * blockDim.x + threadIdx.x;
    if (s >= TK) return;
    int e = g_eid[s];
    if (g_key[s] >= g_thresh[e]) {
        int pos = atomicAdd(&g_cnt[e], 1);
        if (pos < CAP) {
            g_tok[e][pos] = s >> 1;
            g_w[e][pos] = g_val[s];
        }
    }
}

// ======================= GEMM kernels: BK=32, 3-stage, ldmatrix =============
// smem row stride: 40 halves (80B) — conflict-free for ldmatrix & cp.async
#define RS 40

// ---------------- kernel 4: gate_up GEMM (fp16) + SiLU*up -------------------
// stage layout (bytes): A @0 (10240), B @10240 (128 rows: gate 0-63, up 64-127)
#define K4_STG 20480
__global__ __launch_bounds__(256) void k4_gemm1() {
    extern __shared__ char sm[];
    const uint32_t base = saddr(sm);
    const int e = blockIdx.z, m0 = blockIdx.x * 128, n0 = blockIdx.y * 64;
    const int tid = threadIdx.x, warp = tid >> 5, lane = tid & 31;
    const int wm = warp >> 1, wn = warp & 1;
    const int gID = lane >> 2, t4 = lane & 3;

    // loaders
    const int rowA = tid >> 1;
    const int cb = (tid & 1) * 32;           // byte offset within row
    const int chH = cb >> 1;                 // halves
    const int tokA = g_tok[e][m0 + rowA];
    const ushort_t* gx = g_x16 + (size_t)tokA * CDIM + chH;
    const ushort_t* gB = (rowA < 64)
        ? g_wg + ((size_t)e * NP + n0 + rowA) * CDIM + chH
        : g_wu + ((size_t)e * NP + n0 + (rowA - 64)) * CDIM + chH;
    const uint32_t dRow = (uint32_t)(rowA * (RS * 2) + cb);

    auto load = [&](int it, int st) {
        uint32_t s = base + st * K4_STG;
        const ushort_t* ph = gx + it * 32;
        const ushort_t* pb = gB + it * 32;
        cp16(s + dRow,              ph);
        cp16(s + dRow + 16,         ph + 8);
        cp16(s + 10240 + dRow,      pb);
        cp16(s + 10240 + dRow + 16, pb + 8);
        cpcommit();
    };

    // fragment base offsets (bytes within stage)
    const uint32_t aoff = (uint32_t)((wm * 32 + (lane & 15)) * (RS * 2) + ((lane >> 4) * 8) * 2);
    const uint32_t boff = (uint32_t)((((lane & 7) + ((lane >> 4) & 1) * 8)) * (RS * 2) +
                                     (((lane >> 3) & 1) * 8) * 2);

    float acc[2][2][4][4] = {};   // [gu][mt][nt][q]

    const int NIT = CDIM / 32;   // 32
    load(0, 0);
    load(1, 1);

#pragma unroll 1
    for (int it = 0; it < NIT; ++it) {
        if (it + 1 < NIT) cpwait<1>(); else cpwait<0>();
        __syncthreads();
        if (it + 2 < NIT) load(it + 2, (it + 2) % 3);

        const uint32_t s = base + (it % 3) * K4_STG;
#pragma unroll
        for (int ks = 0; ks < 2; ++ks) {
            uint32_t ah[2][4], bb[2][2][4];
#pragma unroll
            for (int mt = 0; mt < 2; ++mt)
                ldsm4(ah[mt], s + aoff + mt * 16 * (RS * 2) + ks * 32);
#pragma unroll
            for (int g = 0; g < 2; ++g)
#pragma unroll
                for (int np = 0; np < 2; ++np)
                    ldsm4(bb[g][np], s + 10240 + boff +
                          (g * 64 + wn * 32 + np * 16) * (RS * 2) + ks * 32);
#pragma unroll
            for (int g = 0; g < 2; ++g)
#pragma unroll
                for (int mt = 0; mt < 2; ++mt)
#pragma unroll
                    for (int nt = 0; nt < 4; ++nt) {
                        const uint32_t* bp = &bb[g][nt >> 1][(nt & 1) * 2];
                        mma16(acc[g][mt][nt], ah[mt], bp);
                    }
        }
        __syncthreads();
    }

    // epilogue: silu(g)*u -> fp16
    ushort_t* pa = g_act + (size_t)e * CAP * AST;
#pragma unroll
    for (int mt = 0; mt < 2; ++mt)
#pragma unroll
        for (int nt = 0; nt < 4; ++nt) {
            int rbase = m0 + wm * 32 + mt * 16 + gID;
            int col = n0 + wn * 32 + nt * 8 + 2 * t4;
            if (col >= INTER) continue;
#pragma unroll
            for (int rq = 0; rq < 2; ++rq) {
                int row = rbase + rq * 8;
                float g0 = acc[0][mt][nt][rq * 2],     u0 = acc[1][mt][nt][rq * 2];
                float g1 = acc[0][mt][nt][rq * 2 + 1], u1 = acc[1][mt][nt][rq * 2 + 1];
                float a0 = __fdividef(g0, 1.0f + __expf(-g0)) * u0;
                float a1 = __fdividef(g1, 1.0f + __expf(-g1)) * u1;
                ushort_t h0 = f2h(a0), h1 = f2h(a1);
                *(uint32_t*)(pa + (size_t)row * AST + col) = (uint32_t)h0 | ((uint32_t)h1 << 16);
            }
        }
}

// ---------------- kernel 5: down GEMM (fp16) + scatter ----------------------
// stage layout: A @0 (10240), B @10240 (64 rows, 5120B)
#define K5_STG 15360
__global__ __launch_bounds__(256) void k5_gemm2(float* __restrict__ out) {
    extern __shared__ char sm[];
    const uint32_t base = saddr(sm);
    const int e = blockIdx.z, m0 = blockIdx.x * 128, n0 = blockIdx.y * 64;
    const int tid = threadIdx.x, warp = tid >> 5, lane = tid & 31;
    const int wm = warp >> 1, wn = warp & 1;
    const int gID = lane >> 2, t4 = lane & 3;

    const int rowA = tid >> 1;
    const int cb = (tid & 1) * 32;
    const int chH = cb >> 1;
    const ushort_t* ga = g_act + ((size_t)e * CAP + m0 + rowA) * AST + chH;
    const uint32_t dRowA = (uint32_t)(rowA * (RS * 2) + cb);

    const int rowB = tid >> 2;
    const int cbB = (tid & 3) * 16;
    const ushort_t* gB = g_wd + ((size_t)e * CDIM + n0 + rowB) * KP + (cbB >> 1);
    const uint32_t dRowB = (uint32_t)(rowB * (RS * 2) + cbB);

    auto load = [&](int it, int st) {
        uint32_t s = base + st * K5_STG;
        const ushort_t* ph = ga + it * 32;
        cp16(s + dRowA,         ph);
        cp16(s + dRowA + 16,    ph + 8);
        cp16(s + 10240 + dRowB, gB + it * 32);
        cpcommit();
    };

    const uint32_t aoff = (uint32_t)((wm * 32 + (lane & 15)) * (RS * 2) + ((lane >> 4) * 8) * 2);
    const uint32_t boff = (uint32_t)((((lane & 7) + ((lane >> 4) & 1) * 8)) * (RS * 2) +
                                     (((lane >> 3) & 1) * 8) * 2);

    float acc[2][4][4] = {};

    const int NIT = KP / 32;   // 86
    load(0, 0);
    load(1, 1);

#pragma unroll 1
    for (int it = 0; it < NIT; ++it) {
        if (it + 1 < NIT) cpwait<1>(); else cpwait<0>();
        __syncthreads();
        if (it + 2 < NIT) load(it + 2, (it + 2) % 3);

        const uint32_t s = base + (it % 3) * K5_STG;
#pragma unroll
        for (int ks = 0; ks < 2; ++ks) {
            uint32_t ah[2][4], bb[2][4];
#pragma unroll
            for (int mt = 0; mt < 2; ++mt)
                ldsm4(ah[mt], s + aoff + mt * 16 * (RS * 2) + ks * 32);
#pragma unroll
            for (int np = 0; np < 2; ++np)
                ldsm4(bb[np], s + 10240 + boff + (wn * 32 + np * 16) * (RS * 2) + ks * 32);
#pragma unroll
            for (int mt = 0; mt < 2; ++mt)
#pragma unroll
                for (int nt = 0; nt < 4; ++nt) {
                    const uint32_t* bp = &bb[nt >> 1][(nt & 1) * 2];
                    mma16(acc[mt][nt], ah[mt], bp);
                }
        }
        __syncthreads();
    }

    // epilogue: scale by routing weight, atomic scatter
#pragma unroll
    for (int mt = 0; mt < 2; ++mt)
#pragma unroll
        for (int rq = 0; rq < 2; ++rq) {
            int row = m0 + wm * 32 + mt * 16 + gID + rq * 8;
            float w = g_w[e][row];
            if (w == 0.0f) continue;
            int tok = g_tok[e][row];
            float* orow = out + (size_t)tok * CDIM;
#pragma unroll
            for (int nt = 0; nt < 4; ++nt) {
                int col = n0 + wn * 32 + nt * 8 + 2 * t4;
                atomicAdd(&orow[col],     acc[mt][nt][rq * 2 + 0] * w);
                atomicAdd(&orow[col + 1], acc[mt][nt][rq * 2 + 1] * w);
            }
        }
}

// ---------------- launch ----------------
extern "C" void kernel_launch(void* const* d_in, const int* in_sizes, int n_in,
                              void* d_out, int out_size) {
    const float* x    = (const float*)d_in[0];
    const float* cond = (const float*)d_in[1];
    const float* snr  = (const float*)d_in[2];
    const float* gw   = (const float*)d_in[3];
    const float* wgu  = (const float*)d_in[4];
    const float* wd   = (const float*)d_in[5];
    float* out = (float*)d_out;

    cudaFuncSetAttribute(k4_gemm1, cudaFuncAttributeMaxDynamicSharedMemorySize, 3 * K4_STG);
    cudaFuncSetAttribute(k5_gemm2, cudaFuncAttributeMaxDynamicSharedMemorySize, 3 * K5_STG);

    k0_init<<<1024, 256>>>(out, out_size);
    ksplit_x<<<2048, 256>>>(x);
    {
        dim3 b(32, 8);
        dim3 g1((N2 + 31) / 32, CDIM / 32, NE);
        ksplit_gu_t<<<g1, b>>>(wgu);
        dim3 g2(CDIM / 32, (INTER + 31) / 32, NE);
        ksplit_dw_t<<<g2, b>>>(wd);
    }
    k1_gate<<<(T_TOK * 32 + 255) / 256, 256>>>(x, cond, snr, gw);
    k2_select<<<NE, 256>>>();
    k3_compact<<<TK / 256, 256>>>();

    dim3 gg1(CAP / 128, NP / 64, NE);    // 20 x 43 x 8
    k4_gemm1<<<gg1, 256, 3 * K4_STG>>>();

    dim3 gg2(CAP / 128, CDIM / 64, NE);  // 20 x 16 x 8
    k5_gemm2<<<gg2, 256, 3 * K5_STG>>>(out);
}

// round 9
// speedup vs baseline: 5.7363x; 1.6176x over previous
#include <cuda_runtime.h>
#include <cuda_fp16.h>
#include <cstdint>
#include <math.h>

// Problem constants
#define T_TOK 16384
#define TK    32768
#define NE    8
#define CDIM  1024
#define INTER 2730
#define N2    5460
#define CAP   2560
#define AST   2752   // activation k-stride (zero tail)
#define NP    2752   // padded n-rows for gate/up transposed weights
#define KP    2752   // padded k-stride for transposed down weights

typedef unsigned short ushort_t;

// ---------------- scratch (device globals; zero-initialized) ----------------
__device__ unsigned long long g_key[TK];
__device__ int   g_eid[TK];
__device__ float g_val[TK];
__device__ unsigned long long g_thresh[NE];
__device__ int   g_cnt[NE];
__device__ int   g_tok[NE][CAP];
__device__ float g_w[NE][CAP];

__device__ ushort_t g_x16[(size_t)T_TOK * CDIM];
__device__ ushort_t g_wg[(size_t)NE * NP * CDIM];    // gate, [e][n][k]
__device__ ushort_t g_wu[(size_t)NE * NP * CDIM];    // up,   [e][n][k]
__device__ ushort_t g_wd[(size_t)NE * CDIM * KP];    // down, [e][n][k]
__device__ ushort_t g_act[(size_t)NE * CAP * AST];

// ---------------- helpers ----------------
__device__ __forceinline__ ushort_t f2h(float f) {
    __half h = __float2half_rn(f);
    return *(ushort_t*)&h;
}
__device__ __forceinline__ uint32_t saddr(const void* p) {
    return (uint32_t)__cvta_generic_to_shared(p);
}
__device__ __forceinline__ void ldsm4(uint32_t* r, uint32_t a) {
    asm volatile("ldmatrix.sync.aligned.m8n8.x4.shared.b16 {%0,%1,%2,%3}, [%4];"
                 : "=r"(r[0]), "=r"(r[1]), "=r"(r[2]), "=r"(r[3]) : "r"(a));
}
__device__ __forceinline__ void mma16(float* c, const uint32_t* a, const uint32_t* b) {
    asm volatile(
        "mma.sync.aligned.m16n8k16.row.col.f32.f16.f16.f32 "
        "{%0,%1,%2,%3},{%4,%5,%6,%7},{%8,%9},{%0,%1,%2,%3};"
        : "+f"(c[0]), "+f"(c[1]), "+f"(c[2]), "+f"(c[3])
        : "r"(a[0]), "r"(a[1]), "r"(a[2]), "r"(a[3]), "r"(b[0]), "r"(b[1]));
}
__device__ __forceinline__ void mbar_init(uint32_t mb) {
    asm volatile("mbarrier.init.shared.b64 [%0], %1;" :: "r"(mb), "r"(1u) : "memory");
}
__device__ __forceinline__ void mbar_expect(uint32_t mb, uint32_t bytes) {
    asm volatile("mbarrier.arrive.expect_tx.shared.b64 _, [%0], %1;"
                 :: "r"(mb), "r"(bytes) : "memory");
}
__device__ __forceinline__ void mbar_wait(uint32_t mb, uint32_t parity) {
    asm volatile(
        "{\n\t.reg .pred P;\n\tWAIT_%=:\n\t"
        "mbarrier.try_wait.parity.acquire.cta.shared::cta.b64 P, [%0], %1, 0x989680;\n\t"
        "@P bra.uni DONE_%=;\n\tbra.uni WAIT_%=;\n\tDONE_%=:\n\t}"
        :: "r"(mb), "r"(parity) : "memory");
}
__device__ __forceinline__ void bulk_cp(uint32_t dst, const void* src,
                                        uint32_t bytes, uint32_t mb) {
    asm volatile(
        "cp.async.bulk.shared::cta.global.mbarrier::complete_tx::bytes [%0], [%1], %2, [%3];"
        :: "r"(dst), "l"(src), "r"(bytes), "r"(mb) : "memory");
}

// ---------------- kernel 0: init ----------------
__global__ void k0_init(float* out, int out_size) {
    int i = blockIdx.x * blockDim.x + threadIdx.x;
    int stride = gridDim.x * blockDim.x;
    for (int j = i; j < out_size; j += stride) out[j] = 0.0f;
    if (i < NE) g_cnt[i] = 0;
    for (int j = i; j < NE * CAP; j += stride) {
        ((int*)g_tok)[j] = 0;
        ((float*)g_w)[j] = 0.0f;
    }
}

// ---------------- convert x -> fp16 ----------------
__global__ void ksplit_x(const float* __restrict__ s) {
    const int n = T_TOK * CDIM;
    int i = blockIdx.x * blockDim.x + threadIdx.x;
    int stride = gridDim.x * blockDim.x;
    for (int j = i * 4; j < n; j += stride * 4) {
        float4 v = *(const float4*)(s + j);
        float* pv = (float*)&v;
        uint32_t h[2];
#pragma unroll
        for (int p = 0; p < 2; ++p) {
            ushort_t h0 = f2h(pv[2*p]);
            ushort_t h1 = f2h(pv[2*p+1]);
            h[p] = (uint32_t)h0 | ((uint32_t)h1 << 16);
        }
        *(uint32_t*)(g_x16 + j)     = h[0];
        *(uint32_t*)(g_x16 + j + 2) = h[1];
    }
}

// ---------------- transpose gate_up_w [e][k][5460] -> fp16 [e][n][k] --------
__global__ void ksplit_gu_t(const float* __restrict__ s) {
    __shared__ float tile[32][33];
    const int e = blockIdx.z;
    const int n0 = blockIdx.x * 32, k0 = blockIdx.y * 32;
    const int tx = threadIdx.x, ty = threadIdx.y;
    for (int i = ty; i < 32; i += 8) {
        int n = n0 + tx, k = k0 + i;
        tile[i][tx] = (n < N2) ? s[((size_t)e * CDIM + k) * N2 + n] : 0.0f;
    }
    __syncthreads();
    for (int i = ty; i < 32; i += 8) {
        int n = n0 + i, k = k0 + tx;
        if (n >= N2) continue;
        ushort_t h = f2h(tile[tx][i]);
        if (n < INTER) {
            g_wg[((size_t)e * NP + n) * CDIM + k] = h;
        } else {
            g_wu[((size_t)e * NP + (n - INTER)) * CDIM + k] = h;
        }
    }
}

// ---------------- transpose down_w [e][k=INTER][n=CDIM] -> fp16 [e][n][k] ---
__global__ void ksplit_dw_t(const float* __restrict__ s) {
    __shared__ float tile[32][33];
    const int e = blockIdx.z;
    const int n0 = blockIdx.x * 32, k0 = blockIdx.y * 32;
    const int tx = threadIdx.x, ty = threadIdx.y;
    for (int i = ty; i < 32; i += 8) {
        int k = k0 + i;
        tile[i][tx] = (k < INTER) ? s[((size_t)e * INTER + k) * CDIM + n0 + tx] : 0.0f;
    }
    __syncthreads();
    for (int i = ty; i < 32; i += 8) {
        int n = n0 + i, k = k0 + tx;
        if (k >= INTER) continue;
        g_wd[((size_t)e * CDIM + n) * KP + k] = f2h(tile[tx][i]);
    }
}

// ---------------- kernel 1: gating (one warp per token) ----------------
__global__ void k1_gate(const float* __restrict__ x, const float* __restrict__ cond,
                        const float* __restrict__ snr, const float* __restrict__ gw) {
    int warp = (blockIdx.x * blockDim.x + threadIdx.x) >> 5;
    int lane = threadIdx.x & 31;
    if (warp >= T_TOK) return;
    int t = warp;
    int b = t >> 12;

    float acc[NE];
#pragma unroll
    for (int e = 0; e < NE; ++e) acc[e] = 0.0f;

    const float* xr = x + (size_t)t * CDIM;
    const float* cr = cond + (size_t)b * CDIM;
    for (int d = lane; d < 2 * CDIM; d += 32) {
        float v = (d < CDIM) ? xr[d] : cr[d - CDIM];
        const float* wrow = gw + (size_t)d * NE;
#pragma unroll
        for (int e = 0; e < NE; ++e) acc[e] += v * wrow[e];
    }
#pragma unroll
    for (int e = 0; e < NE; ++e) {
#pragma unroll
        for (int o = 16; o > 0; o >>= 1)
            acc[e] += __shfl_xor_sync(0xFFFFFFFFu, acc[e], o);
    }

    if (lane == 0) {
        bool hn = snr[b] < 0.5f;
        float lg[NE];
#pragma unroll
        for (int e = 0; e < NE; ++e)
            lg[e] = (hn && e >= 2) ? -INFINITY : acc[e];

        float mx = lg[0];
#pragma unroll
        for (int e = 1; e < NE; ++e) mx = fmaxf(mx, lg[e]);
        float p[NE], s = 0.0f;
#pragma unroll
        for (int e = 0; e < NE; ++e) { p[e] = expf(lg[e] - mx); s += p[e]; }
        float inv = 1.0f / s;
#pragma unroll
        for (int e = 0; e < NE; ++e) p[e] *= inv;

        int i0 = 0; float p0 = p[0];
#pragma unroll
        for (int e = 1; e < NE; ++e) if (p[e] > p0) { p0 = p[e]; i0 = e; }
        int i1 = -1; float p1 = -1.0f;
#pragma unroll
        for (int e = 0; e < NE; ++e) if (e != i0 && p[e] > p1) { p1 = p[e]; i1 = e; }

        float denom = fmaxf(p0 + p1, 1e-12f);
        float w0 = p0 / denom, w1 = p1 / denom;

        int s0 = t * 2, s1 = t * 2 + 1;
        g_eid[s0] = i0; g_val[s0] = w0;
        g_key[s0] = ((unsigned long long)__float_as_uint(w0) << 32) |
                    (unsigned long long)(0xFFFFFFFFu - (unsigned)s0);
        g_eid[s1] = i1; g_val[s1] = w1;
        g_key[s1] = ((unsigned long long)__float_as_uint(w1) << 32) |
                    (unsigned long long)(0xFFFFFFFFu - (unsigned)s1);
    }
}

// ---------------- kernel 2: per-expert exact radix select ----------------
__global__ void k2_select() {
    int e = blockIdx.x;
    int tid = threadIdx.x;
    __shared__ int hist[256];
    __shared__ unsigned long long sh_prefix;
    __shared__ int sh_rem;
    __shared__ int sh_n;

    int cnt = 0;
    for (int s = tid; s < TK; s += 256) if (g_eid[s] == e) cnt++;
    if (tid == 0) sh_n = 0;
    __syncthreads();
    atomicAdd(&sh_n, cnt);
    __syncthreads();
    int n = sh_n;

    if (n <= CAP) {
        if (tid == 0) g_thresh[e] = 0ULL;
        return;
    }

    if (tid == 0) { sh_prefix = 0ULL; sh_rem = CAP; }
    __syncthreads();

    for (int p = 7; p >= 0; --p) {
        if (tid < 256) hist[tid] = 0;
        __syncthreads();
        unsigned long long prefix = sh_prefix;
        int shift_lo = p * 8;
        for (int s = tid; s < TK; s += 256) {
            if (g_eid[s] != e) continue;
            unsigned long long key = g_key[s];
            bool match = (p == 7) || (((key ^ prefix) >> ((p + 1) * 8)) == 0ULL);
            if (match)
                atomicAdd(&hist[(int)((key >> shift_lo) & 255ULL)], 1);
        }
        __syncthreads();
        if (tid == 0) {
            int rem = sh_rem;
            int cum = 0, d = 255;
            for (; d > 0; --d) { cum += hist[d]; if (cum >= rem) break; }
            if (cum < rem) cum += hist[0];
            sh_prefix |= ((unsigned long long)d) << shift_lo;
            sh_rem = rem - (cum - hist[d]);
        }
        __syncthreads();
    }
    if (tid == 0) g_thresh[e] = sh_prefix;
}

// ---------------- kernel 3: compaction ----------------
__global__ void k3_compact() {
    int s = blockIdx.x * blockDim.x + threadIdx.x;
    if (s >= TK) return;
    int e = g_eid[s];
    if (g_key[s] >= g_thresh[e]) {
        int pos = atomicAdd(&g_cnt[e], 1);
        if (pos < CAP) {
            g_tok[e][pos] = s >> 1;
            g_w[e][pos] = g_val[s];
        }
    }
}

// ======== GEMM kernels: BK=64, 2-stage bulk-copy pipeline, ldmatrix =========
// smem row slot: 144 bytes (128B data + 16B pad) — ldmatrix conflict-free
#define RS2 144

// ---------------- kernel 4: gate_up GEMM (fp16) + SiLU*up -------------------
#define K4_STG   (256 * RS2)    // 36864 bytes per stage
#define K4_BYTES (256 * 128)    // 32768 expected tx per stage
__global__ __launch_bounds__(256) void k4_gemm1() {
    extern __shared__ char sm[];
    const uint32_t base = saddr(sm);
    const uint32_t mb0 = base;          // two mbarriers @0, @8
    const uint32_t tiles = base + 16;
    const int e = blockIdx.z, m0 = blockIdx.x * 128, n0 = blockIdx.y * 64;
    const int tid = threadIdx.x, warp = tid >> 5, lane = tid & 31;
    const int wm = warp >> 1, wn = warp & 1;
    const int gID = lane >> 2, t4 = lane & 3;

    if (tid == 0) { mbar_init(mb0); mbar_init(mb0 + 8); }

    // per-thread source row: tid<128 -> A (token rows), else B (gate/up rows)
    const ushort_t* srcRow;
    if (tid < 128) {
        int tok = g_tok[e][m0 + tid];
        srcRow = g_x16 + (size_t)tok * CDIM;
    } else {
        int r = tid - 128;
        srcRow = (r < 64)
            ? g_wg + ((size_t)e * NP + n0 + r) * CDIM
            : g_wu + ((size_t)e * NP + n0 + (r - 64)) * CDIM;
    }
    const uint32_t dstOff = tiles + (uint32_t)tid * RS2;
    __syncthreads();

    auto fill = [&](int it) {
        int s = it & 1;
        if (tid == 0) mbar_expect(mb0 + s * 8, K4_BYTES);
        bulk_cp(dstOff + s * K4_STG, srcRow + it * 64, 128, mb0 + s * 8);
    };

    // fragment offsets (bytes within stage)
    const uint32_t aoffr = (uint32_t)((wm * 32 + (lane & 15)) * RS2 + (lane >> 4) * 16);
    const uint32_t boffr = (uint32_t)(128 * RS2 +
                            ((lane & 7) + ((lane >> 4) & 1) * 8) * RS2 +
                            ((lane >> 3) & 1) * 16);

    float acc[2][2][4][4] = {};   // [gu][mt][nt][q]

    const int NIT = CDIM / 64;   // 16
    fill(0); fill(1);

#pragma unroll 1
    for (int it = 0; it < NIT; ++it) {
        mbar_wait(mb0 + (it & 1) * 8, (uint32_t)((it >> 1) & 1));
        const uint32_t s = tiles + (it & 1) * K4_STG;
#pragma unroll
        for (int ks = 0; ks < 4; ++ks) {
            uint32_t ah[2][4], bb[2][2][4];
#pragma unroll
            for (int mt = 0; mt < 2; ++mt)
                ldsm4(ah[mt], s + aoffr + mt * 16 * RS2 + ks * 32);
#pragma unroll
            for (int g = 0; g < 2; ++g)
#pragma unroll
                for (int np = 0; np < 2; ++np)
                    ldsm4(bb[g][np], s + boffr + (g * 64 + wn * 32 + np * 16) * RS2 + ks * 32);
#pragma unroll
            for (int g = 0; g < 2; ++g)
#pragma unroll
                for (int mt = 0; mt < 2; ++mt)
#pragma unroll
                    for (int nt = 0; nt < 4; ++nt) {
                        const uint32_t* bp = &bb[g][nt >> 1][(nt & 1) * 2];
                        mma16(acc[g][mt][nt], ah[mt], bp);
                    }
        }
        __syncthreads();
        if (it + 2 < NIT) fill(it + 2);
    }

    // epilogue: silu(g)*u -> fp16
    ushort_t* pa = g_act + (size_t)e * CAP * AST;
#pragma unroll
    for (int mt = 0; mt < 2; ++mt)
#pragma unroll
        for (int nt = 0; nt < 4; ++nt) {
            int rbase = m0 + wm * 32 + mt * 16 + gID;
            int col = n0 + wn * 32 + nt * 8 + 2 * t4;
            if (col >= INTER) continue;
#pragma unroll
            for (int rq = 0; rq < 2; ++rq) {
                int row = rbase + rq * 8;
                float g0 = acc[0][mt][nt][rq * 2],     u0 = acc[1][mt][nt][rq * 2];
                float g1 = acc[0][mt][nt][rq * 2 + 1], u1 = acc[1][mt][nt][rq * 2 + 1];
                float a0 = __fdividef(g0, 1.0f + __expf(-g0)) * u0;
                float a1 = __fdividef(g1, 1.0f + __expf(-g1)) * u1;
                ushort_t h0 = f2h(a0), h1 = f2h(a1);
                *(uint32_t*)(pa + (size_t)row * AST + col) = (uint32_t)h0 | ((uint32_t)h1 << 16);
            }
        }
}

// ---------------- kernel 5: down GEMM (fp16) + scatter ----------------------
#define K5_STG   (192 * RS2)    // 27648 bytes per stage
#define K5_BYTES (192 * 128)    // 24576 expected tx per stage
__global__ __launch_bounds__(256) void k5_gemm2(float* __restrict__ out) {
    extern __shared__ char sm[];
    const uint32_t base = saddr(sm);
    const uint32_t mb0 = base;
    const uint32_t tiles = base + 16;
    const int e = blockIdx.z, m0 = blockIdx.x * 128, n0 = blockIdx.y * 64;
    const int tid = threadIdx.x, warp = tid >> 5, lane = tid & 31;
    const int wm = warp >> 1, wn = warp & 1;
    const int gID = lane >> 2, t4 = lane & 3;

    if (tid == 0) { mbar_init(mb0); mbar_init(mb0 + 8); }

    const ushort_t* srcRow = nullptr;
    if (tid < 128) {
        srcRow = g_act + ((size_t)e * CAP + m0 + tid) * AST;
    } else if (tid < 192) {
        srcRow = g_wd + ((size_t)e * CDIM + n0 + (tid - 128)) * KP;
    }
    const uint32_t dstOff = tiles + (uint32_t)tid * RS2;
    __syncthreads();

    auto fill = [&](int it) {
        int s = it & 1;
        if (tid == 0) mbar_expect(mb0 + s * 8, K5_BYTES);
        if (tid < 192) bulk_cp(dstOff + s * K5_STG, srcRow + it * 64, 128, mb0 + s * 8);
    };

    const uint32_t aoffr = (uint32_t)((wm * 32 + (lane & 15)) * RS2 + (lane >> 4) * 16);
    const uint32_t boffr = (uint32_t)(128 * RS2 +
                            ((lane & 7) + ((lane >> 4) & 1) * 8) * RS2 +
                            ((lane >> 3) & 1) * 16);

    float acc[2][4][4] = {};

    const int NIT = KP / 64;   // 43
    fill(0); fill(1);

#pragma unroll 1
    for (int it = 0; it < NIT; ++it) {
        mbar_wait(mb0 + (it & 1) * 8, (uint32_t)((it >> 1) & 1));
        const uint32_t s = tiles + (it & 1) * K5_STG;
#pragma unroll
        for (int ks = 0; ks < 4; ++ks) {
            uint32_t ah[2][4], bb[2][4];
#pragma unroll
            for (int mt = 0; mt < 2; ++mt)
                ldsm4(ah[mt], s + aoffr + mt * 16 * RS2 + ks * 32);
#pragma unroll
            for (int np = 0; np < 2; ++np)
                ldsm4(bb[np], s + boffr + (wn * 32 + np * 16) * RS2 + ks * 32);
#pragma unroll
            for (int mt = 0; mt < 2; ++mt)
#pragma unroll
                for (int nt = 0; nt < 4; ++nt) {
                    const uint32_t* bp = &bb[nt >> 1][(nt & 1) * 2];
                    mma16(acc[mt][nt], ah[mt], bp);
                }
        }
        __syncthreads();
        if (it + 2 < NIT) fill(it + 2);
    }

    // epilogue: scale by routing weight, atomic scatter
#pragma unroll
    for (int mt = 0; mt < 2; ++mt)
#pragma unroll
        for (int rq = 0; rq < 2; ++rq) {
            int row = m0 + wm * 32 + mt * 16 + gID + rq * 8;
            float w = g_w[e][row];
            if (w == 0.0f) continue;
            int tok = g_tok[e][row];
            float* orow = out + (size_t)tok * CDIM;
#pragma unroll
            for (int nt = 0; nt < 4; ++nt) {
                int col = n0 + wn * 32 + nt * 8 + 2 * t4;
                atomicAdd(&orow[col],     acc[mt][nt][rq * 2 + 0] * w);
                atomicAdd(&orow[col + 1], acc[mt][nt][rq * 2 + 1] * w);
            }
        }
}

// ---------------- launch ----------------
extern "C" void kernel_launch(void* const* d_in, const int* in_sizes, int n_in,
                              void* d_out, int out_size) {
    const float* x    = (const float*)d_in[0];
    const float* cond = (const float*)d_in[1];
    const float* snr  = (const float*)d_in[2];
    const float* gw   = (const float*)d_in[3];
    const float* wgu  = (const float*)d_in[4];
    const float* wd   = (const float*)d_in[5];
    float* out = (float*)d_out;

    const int SM4 = 16 + 2 * K4_STG;   // 73744
    const int SM5 = 16 + 2 * K5_STG;   // 55312
    cudaFuncSetAttribute(k4_gemm1, cudaFuncAttributeMaxDynamicSharedMemorySize, SM4);
    cudaFuncSetAttribute(k5_gemm2, cudaFuncAttributeMaxDynamicSharedMemorySize, SM5);

    k0_init<<<1024, 256>>>(out, out_size);
    ksplit_x<<<2048, 256>>>(x);
    {
        dim3 b(32, 8);
        dim3 g1((N2 + 31) / 32, CDIM / 32, NE);
        ksplit_gu_t<<<g1, b>>>(wgu);
        dim3 g2(CDIM / 32, (INTER + 31) / 32, NE);
        ksplit_dw_t<<<g2, b>>>(wd);
    }
    k1_gate<<<(T_TOK * 32 + 255) / 256, 256>>>(x, cond, snr, gw);
    k2_select<<<NE, 256>>>();
    k3_compact<<<TK / 256, 256>>>();

    dim3 gg1(CAP / 128, NP / 64, NE);    // 20 x 43 x 8
    k4_gemm1<<<gg1, 256, SM4>>>();

    dim3 gg2(CAP / 128, CDIM / 64, NE);  // 20 x 16 x 8
    k5_gemm2<<<gg2, 256, SM5>>>(out);
}